// round 1
// baseline (speedup 1.0000x reference)
#include <cuda_runtime.h>
#include <math.h>

#define NE 8
#define DIM 1024
#define IDIM 2048
#define TKN_MAX 8192
#define ASG_MAX 16384

// ---------------- device scratch (no allocs allowed) ----------------
__device__ float g_G[(size_t)ASG_MAX * IDIM];     // 128 MB: gate/H intermediate (shared uses rows [0,T))
__device__ float g_pair[(size_t)ASG_MAX * DIM];   // 64 MB: per-assignment routed output
__device__ int   g_assign[ASG_MAX];               // assignment -> token
__device__ int   g_te[ASG_MAX];                   // token -> 2 expert ids
__device__ float g_tw[ASG_MAX];                   // token -> 2 weights
__device__ int   g_slot[ASG_MAX];                 // token -> 2 assignment positions
__device__ int   g_counts[NE];
__device__ int   g_off[NE + 1];
__device__ int   g_cursor[NE];
__device__ float g_psum[NE];

// ---------------- init ----------------
__global__ void k_init() {
    int i = threadIdx.x;
    if (i < NE) { g_counts[i] = 0; g_psum[i] = 0.f; }
}

// ---------------- router: logits, top-2, softmax weights, aux partials ----------------
__global__ void k_router(const float* __restrict__ x, const float* __restrict__ gw, int T) {
    __shared__ float sP[NE];
    if (threadIdx.x < NE) sP[threadIdx.x] = 0.f;
    __syncthreads();

    int warp = (blockIdx.x * blockDim.x + threadIdx.x) >> 5;
    int lane = threadIdx.x & 31;
    if (warp < T) {
        const float* xr = x + (size_t)warp * DIM;
        float acc[NE];
#pragma unroll
        for (int e = 0; e < NE; e++) acc[e] = 0.f;
        for (int i = lane; i < DIM; i += 32) {
            float xv = xr[i];
#pragma unroll
            for (int e = 0; e < NE; e++) acc[e] = fmaf(xv, gw[e * DIM + i], acc[e]);
        }
#pragma unroll
        for (int e = 0; e < NE; e++) {
#pragma unroll
            for (int o = 16; o; o >>= 1) acc[e] += __shfl_xor_sync(0xffffffffu, acc[e], o);
        }
        if (lane == 0) {
            // full softmax for P (aux loss)
            float mx = acc[0];
#pragma unroll
            for (int e = 1; e < NE; e++) mx = fmaxf(mx, acc[e]);
            float ex[NE]; float s = 0.f;
#pragma unroll
            for (int e = 0; e < NE; e++) { ex[e] = expf(acc[e] - mx); s += ex[e]; }
            float inv = 1.f / s;
#pragma unroll
            for (int e = 0; e < NE; e++) atomicAdd(&sP[e], ex[e] * inv);
            // top-2 (ties -> lowest index, matching jax.lax.top_k)
            int i0 = 0;
#pragma unroll
            for (int e = 1; e < NE; e++) if (acc[e] > acc[i0]) i0 = e;
            int i1 = (i0 == 0) ? 1 : 0;
#pragma unroll
            for (int e = 0; e < NE; e++) if (e != i0 && acc[e] > acc[i1]) i1 = e;
            float m2 = fmaxf(acc[i0], acc[i1]);
            float e0 = expf(acc[i0] - m2), e1 = expf(acc[i1] - m2);
            float wsum = e0 + e1;
            g_te[2 * warp] = i0; g_te[2 * warp + 1] = i1;
            g_tw[2 * warp] = e0 / wsum; g_tw[2 * warp + 1] = e1 / wsum;
            atomicAdd(&g_counts[i0], 1);
            atomicAdd(&g_counts[i1], 1);
        }
    }
    __syncthreads();
    if (threadIdx.x < NE) atomicAdd(&g_psum[threadIdx.x], sP[threadIdx.x]);
}

// ---------------- scan: offsets, cursors, aux loss ----------------
__global__ void k_scan(float* __restrict__ out, int T, int write_aux) {
    if (threadIdx.x == 0 && blockIdx.x == 0) {
        int o = 0;
        float aux = 0.f;
        for (int e = 0; e < NE; e++) {
            g_off[e] = o; g_cursor[e] = o;
            float f = (float)g_counts[e] / (float)(T * 2);
            float P = g_psum[e] / (float)T;
            aux += f * P;
            o += g_counts[e];
        }
        g_off[NE] = o;
        if (write_aux) out[(size_t)T * DIM] = (float)NE * aux;
    }
}

// ---------------- scatter: per-expert assignment lists ----------------
__global__ void k_scatter(int T) {
    int t = blockIdx.x * blockDim.x + threadIdx.x;
    if (t < T) {
#pragma unroll
        for (int k = 0; k < 2; k++) {
            int e = g_te[2 * t + k];
            int pos = atomicAdd(&g_cursor[e], 1);
            g_assign[pos] = t;
            g_slot[2 * t + k] = pos;
        }
    }
}

// ---------------- generic segmented / gathered SGEMM ----------------
// C[m, n0:n0+128] = A[rid(m), :K] @ B_seg[:, n0:n0+128]
// EPI==1: C = silu(Gbuf[m,n]) * acc   (swiglu combine; Gbuf holds gate-proj)
template <int EPI>
__global__ __launch_bounds__(256, 2) void k_gemm(
    const float* __restrict__ A, const float* __restrict__ Bmat, float* __restrict__ C,
    const int* __restrict__ row_ids, const int* __restrict__ seg_off,
    int M, int N, int K, long strideB, const float* __restrict__ Gbuf)
{
    int m_lo = 0, m_hi = M;
    const float* Bp = Bmat;
    if (seg_off) {
        int s = blockIdx.z;
        m_lo = seg_off[s]; m_hi = seg_off[s + 1];
        Bp += (long)s * strideB;
    }
    int m0 = m_lo + blockIdx.y * 128;
    if (m0 >= m_hi) return;
    int n0 = blockIdx.x * 128;

    __shared__ float As[8][128];
    __shared__ float Bs[8][128];

    int tid = threadIdx.x;
    int a_row = tid >> 1;
    int a_k = (tid & 1) << 2;
    int b_k = tid >> 5;
    int b_n = (tid & 31) << 2;
    int tx = tid & 15, ty = tid >> 4;

    const float* Arow = A;
    bool avalid = (m0 + a_row) < m_hi;
    if (avalid) {
        int gm = m0 + a_row;
        int rid = row_ids ? row_ids[gm] : gm;
        Arow = A + (size_t)rid * K;
    }

    float acc[8][8];
#pragma unroll
    for (int i = 0; i < 8; i++)
#pragma unroll
        for (int j = 0; j < 8; j++) acc[i][j] = 0.f;

    for (int k0 = 0; k0 < K; k0 += 8) {
        float4 av = avalid ? *(const float4*)(Arow + k0 + a_k) : make_float4(0.f, 0.f, 0.f, 0.f);
        As[a_k + 0][a_row] = av.x;
        As[a_k + 1][a_row] = av.y;
        As[a_k + 2][a_row] = av.z;
        As[a_k + 3][a_row] = av.w;
        *(float4*)&Bs[b_k][b_n] = *(const float4*)(Bp + (size_t)(k0 + b_k) * N + n0 + b_n);
        __syncthreads();
#pragma unroll
        for (int kk = 0; kk < 8; kk++) {
            float ar[8], br[8];
            *(float4*)&ar[0] = *(const float4*)&As[kk][ty * 8];
            *(float4*)&ar[4] = *(const float4*)&As[kk][ty * 8 + 4];
            *(float4*)&br[0] = *(const float4*)&Bs[kk][tx * 8];
            *(float4*)&br[4] = *(const float4*)&Bs[kk][tx * 8 + 4];
#pragma unroll
            for (int i = 0; i < 8; i++)
#pragma unroll
                for (int j = 0; j < 8; j++) acc[i][j] = fmaf(ar[i], br[j], acc[i][j]);
        }
        __syncthreads();
    }

#pragma unroll
    for (int i = 0; i < 8; i++) {
        int m = m0 + ty * 8 + i;
        if (m >= m_hi) continue;
        size_t base = (size_t)m * N + n0 + tx * 8;
#pragma unroll
        for (int jj = 0; jj < 8; jj += 4) {
            float4 v = make_float4(acc[i][jj], acc[i][jj + 1], acc[i][jj + 2], acc[i][jj + 3]);
            if (EPI == 1) {
                float4 g = *(const float4*)(Gbuf + base + jj);
                v.x *= g.x / (1.f + expf(-g.x));
                v.y *= g.y / (1.f + expf(-g.y));
                v.z *= g.z / (1.f + expf(-g.z));
                v.w *= g.w / (1.f + expf(-g.w));
            }
            *(float4*)(C + base + jj) = v;
        }
    }
}

// ---------------- combine: out = shared + w0*pair[slot0] + w1*pair[slot1] ----------------
__global__ void k_combine(float* __restrict__ out, const float* __restrict__ pair, int T) {
    int t = blockIdx.x;
    float w0 = g_tw[2 * t], w1 = g_tw[2 * t + 1];
    size_t p0 = (size_t)g_slot[2 * t] * DIM;
    size_t p1 = (size_t)g_slot[2 * t + 1] * DIM;
    size_t ob = (size_t)t * DIM;
    for (int d = threadIdx.x * 4; d < DIM; d += blockDim.x * 4) {
        float4 a = *(const float4*)(pair + p0 + d);
        float4 b = *(const float4*)(pair + p1 + d);
        float4 o = *(const float4*)(out + ob + d);
        o.x += w0 * a.x + w1 * b.x;
        o.y += w0 * a.y + w1 * b.y;
        o.z += w0 * a.z + w1 * b.z;
        o.w += w0 * a.w + w1 * b.w;
        *(float4*)(out + ob + d) = o;
    }
}

// ---------------- launch ----------------
extern "C" void kernel_launch(void* const* d_in, const int* in_sizes, int n_in,
                              void* d_out, int out_size) {
    const float* x  = (const float*)d_in[0];
    const float* gw = (const float*)d_in[1];
    const float* sg = (const float*)d_in[2];
    const float* su = (const float*)d_in[3];
    const float* sd = (const float*)d_in[4];
    const float* eg = (const float*)d_in[5];
    const float* eu = (const float*)d_in[6];
    const float* ed = (const float*)d_in[7];
    float* out = (float*)d_out;

    int T = in_sizes[0] / DIM;       // 8192
    int A2 = 2 * T;                  // total assignments

    float *pG, *pPair;
    int *pAssign, *pOff;
    cudaGetSymbolAddress((void**)&pG, g_G);
    cudaGetSymbolAddress((void**)&pPair, g_pair);
    cudaGetSymbolAddress((void**)&pAssign, g_assign);
    cudaGetSymbolAddress((void**)&pOff, g_off);

    k_init<<<1, 32>>>();
    k_router<<<(T + 7) / 8, 256>>>(x, gw, T);
    k_scan<<<1, 1>>>(out, T, (size_t)out_size > (size_t)T * DIM ? 1 : 0);
    k_scatter<<<(T + 255) / 256, 256>>>(T);

    // shared expert: G = x@Wg ; H = silu(G)*(x@Wu) ; out = H@Wd
    k_gemm<0><<<dim3(IDIM / 128, T / 128, 1), 256>>>(x, sg, pG, nullptr, nullptr, T, IDIM, DIM, 0, nullptr);
    k_gemm<1><<<dim3(IDIM / 128, T / 128, 1), 256>>>(x, su, pG, nullptr, nullptr, T, IDIM, DIM, 0, pG);
    k_gemm<0><<<dim3(DIM / 128, T / 128, 1), 256>>>(pG, sd, out, nullptr, nullptr, T, DIM, IDIM, 0, nullptr);

    // routed experts (gathered rows, per-expert weights, worst-case grid.y; empty tiles exit)
    int mt = (A2 + 127) / 128;
    k_gemm<0><<<dim3(IDIM / 128, mt, NE), 256>>>(x, eg, pG, pAssign, pOff, A2, IDIM, DIM, (long)DIM * IDIM, nullptr);
    k_gemm<1><<<dim3(IDIM / 128, mt, NE), 256>>>(x, eu, pG, pAssign, pOff, A2, IDIM, DIM, (long)DIM * IDIM, pG);
    k_gemm<0><<<dim3(DIM / 128, mt, NE), 256>>>(pG, ed, pPair, nullptr, pOff, A2, DIM, IDIM, (long)IDIM * DIM, nullptr);

    k_combine<<<T, 256>>>(out, pPair, T);
}

// round 2
// speedup vs baseline: 1.0607x; 1.0607x over previous
#include <cuda_runtime.h>
#include <math.h>

#define NE 8
#define DIM 1024
#define IDIM 2048
#define TKN_MAX 8192
#define ASG_MAX 16384

// ---------------- device scratch (no allocs allowed) ----------------
__device__ float g_G[(size_t)ASG_MAX * IDIM];     // 128 MB: gate/H intermediate (shared uses rows [0,T))
__device__ float g_pair[(size_t)ASG_MAX * DIM];   // 64 MB: per-assignment routed output
__device__ int   g_assign[ASG_MAX];               // assignment -> token
__device__ int   g_te[ASG_MAX];                   // token -> 2 expert ids
__device__ float g_tw[ASG_MAX];                   // token -> 2 weights
__device__ int   g_slot[ASG_MAX];                 // token -> 2 assignment positions
__device__ int   g_counts[NE];
__device__ int   g_off[NE + 1];
__device__ int   g_cursor[NE];
__device__ float g_psum[NE];

// ---------------- packed f32x2 helpers (sm_103a FFMA2 path) ----------------
__device__ __forceinline__ void ffma2(unsigned long long& d, unsigned long long a, unsigned long long b) {
    asm("fma.rn.f32x2 %0, %1, %2, %0;" : "+l"(d) : "l"(a), "l"(b));
}
__device__ __forceinline__ unsigned long long pack2(float x) {
    unsigned long long d;
    asm("mov.b64 %0, {%1, %1};" : "=l"(d) : "f"(x));
    return d;
}
__device__ __forceinline__ float lo32(unsigned long long v) {
    return __uint_as_float((unsigned)(v & 0xffffffffull));
}
__device__ __forceinline__ float hi32(unsigned long long v) {
    return __uint_as_float((unsigned)(v >> 32));
}

// ---------------- init ----------------
__global__ void k_init() {
    int i = threadIdx.x;
    if (i < NE) { g_counts[i] = 0; g_psum[i] = 0.f; }
}

// ---------------- router: logits, top-2, softmax weights, aux partials ----------------
__global__ void k_router(const float* __restrict__ x, const float* __restrict__ gw, int T) {
    __shared__ float sP[NE];
    if (threadIdx.x < NE) sP[threadIdx.x] = 0.f;
    __syncthreads();

    int warp = (blockIdx.x * blockDim.x + threadIdx.x) >> 5;
    int lane = threadIdx.x & 31;
    if (warp < T) {
        const float* xr = x + (size_t)warp * DIM;
        float acc[NE];
#pragma unroll
        for (int e = 0; e < NE; e++) acc[e] = 0.f;
        for (int i = lane; i < DIM; i += 32) {
            float xv = xr[i];
#pragma unroll
            for (int e = 0; e < NE; e++) acc[e] = fmaf(xv, gw[e * DIM + i], acc[e]);
        }
#pragma unroll
        for (int e = 0; e < NE; e++) {
#pragma unroll
            for (int o = 16; o; o >>= 1) acc[e] += __shfl_xor_sync(0xffffffffu, acc[e], o);
        }
        if (lane == 0) {
            // full softmax for P (aux loss)
            float mx = acc[0];
#pragma unroll
            for (int e = 1; e < NE; e++) mx = fmaxf(mx, acc[e]);
            float ex[NE]; float s = 0.f;
#pragma unroll
            for (int e = 0; e < NE; e++) { ex[e] = expf(acc[e] - mx); s += ex[e]; }
            float inv = 1.f / s;
#pragma unroll
            for (int e = 0; e < NE; e++) atomicAdd(&sP[e], ex[e] * inv);
            // top-2 (ties -> lowest index, matching jax.lax.top_k)
            int i0 = 0;
#pragma unroll
            for (int e = 1; e < NE; e++) if (acc[e] > acc[i0]) i0 = e;
            int i1 = (i0 == 0) ? 1 : 0;
#pragma unroll
            for (int e = 0; e < NE; e++) if (e != i0 && acc[e] > acc[i1]) i1 = e;
            float m2 = fmaxf(acc[i0], acc[i1]);
            float e0 = expf(acc[i0] - m2), e1 = expf(acc[i1] - m2);
            float wsum = e0 + e1;
            g_te[2 * warp] = i0; g_te[2 * warp + 1] = i1;
            g_tw[2 * warp] = e0 / wsum; g_tw[2 * warp + 1] = e1 / wsum;
            atomicAdd(&g_counts[i0], 1);
            atomicAdd(&g_counts[i1], 1);
        }
    }
    __syncthreads();
    if (threadIdx.x < NE) atomicAdd(&g_psum[threadIdx.x], sP[threadIdx.x]);
}

// ---------------- scan: offsets, cursors, aux loss ----------------
__global__ void k_scan(float* __restrict__ out, int T, int write_aux) {
    if (threadIdx.x == 0 && blockIdx.x == 0) {
        int o = 0;
        float aux = 0.f;
        for (int e = 0; e < NE; e++) {
            g_off[e] = o; g_cursor[e] = o;
            float f = (float)g_counts[e] / (float)(T * 2);
            float P = g_psum[e] / (float)T;
            aux += f * P;
            o += g_counts[e];
        }
        g_off[NE] = o;
        if (write_aux) out[(size_t)T * DIM] = (float)NE * aux;
    }
}

// ---------------- scatter: per-expert assignment lists ----------------
__global__ void k_scatter(int T) {
    int t = blockIdx.x * blockDim.x + threadIdx.x;
    if (t < T) {
#pragma unroll
        for (int k = 0; k < 2; k++) {
            int e = g_te[2 * t + k];
            int pos = atomicAdd(&g_cursor[e], 1);
            g_assign[pos] = t;
            g_slot[2 * t + k] = pos;
        }
    }
}

// ---------------- generic segmented / gathered SGEMM (FFMA2 inner loop) ----------------
// C[m, n0:n0+128] = A[rid(m), :K] @ B_seg[:, n0:n0+128]
// EPI==1: C = silu(Gbuf[m,n]) * acc   (swiglu combine; Gbuf holds gate-proj)
template <int EPI>
__global__ __launch_bounds__(256, 2) void k_gemm(
    const float* __restrict__ A, const float* __restrict__ Bmat, float* __restrict__ C,
    const int* __restrict__ row_ids, const int* __restrict__ seg_off,
    int M, int N, int K, long strideB, const float* __restrict__ Gbuf)
{
    int m_lo = 0, m_hi = M;
    const float* Bp = Bmat;
    if (seg_off) {
        int s = blockIdx.z;
        m_lo = seg_off[s]; m_hi = seg_off[s + 1];
        Bp += (long)s * strideB;
    }
    int m0 = m_lo + blockIdx.y * 128;
    if (m0 >= m_hi) return;
    int n0 = blockIdx.x * 128;

    __shared__ float As[8][128];
    __shared__ float Bs[8][128];

    int tid = threadIdx.x;
    int a_row = tid >> 1;
    int a_k = (tid & 1) << 2;
    int b_k = tid >> 5;
    int b_n = (tid & 31) << 2;
    int tx = tid & 15, ty = tid >> 4;

    const float* Arow = A;
    bool avalid = (m0 + a_row) < m_hi;
    if (avalid) {
        int gm = m0 + a_row;
        int rid = row_ids ? row_ids[gm] : gm;
        Arow = A + (size_t)rid * K;
    }
    const float* Bld = Bp + (size_t)b_k * N + n0 + b_n;

    unsigned long long acc2[8][4];
#pragma unroll
    for (int i = 0; i < 8; i++)
#pragma unroll
        for (int p = 0; p < 4; p++) acc2[i][p] = 0ull;

    // prologue: prefetch tile 0 into registers
    float4 av = avalid ? *(const float4*)(Arow + a_k) : make_float4(0.f, 0.f, 0.f, 0.f);
    float4 bv = *(const float4*)(Bld);

    for (int k0 = 0; k0 < K; k0 += 8) {
        As[a_k + 0][a_row] = av.x;
        As[a_k + 1][a_row] = av.y;
        As[a_k + 2][a_row] = av.z;
        As[a_k + 3][a_row] = av.w;
        *(float4*)&Bs[b_k][b_n] = bv;
        __syncthreads();

        // prefetch next tile while computing this one
        if (k0 + 8 < K) {
            if (avalid) av = *(const float4*)(Arow + k0 + 8 + a_k);
            bv = *(const float4*)(Bld + (size_t)(k0 + 8) * N);
        }

#pragma unroll
        for (int kk = 0; kk < 8; kk++) {
            float ar[8];
            *(float4*)&ar[0] = *(const float4*)&As[kk][ty * 8];
            *(float4*)&ar[4] = *(const float4*)&As[kk][ty * 8 + 4];
            const unsigned long long* Bd = (const unsigned long long*)&Bs[kk][tx * 8];
            unsigned long long bd0 = Bd[0], bd1 = Bd[1], bd2 = Bd[2], bd3 = Bd[3];
#pragma unroll
            for (int i = 0; i < 8; i++) {
                unsigned long long ad = pack2(ar[i]);
                ffma2(acc2[i][0], ad, bd0);
                ffma2(acc2[i][1], ad, bd1);
                ffma2(acc2[i][2], ad, bd2);
                ffma2(acc2[i][3], ad, bd3);
            }
        }
        __syncthreads();
    }

#pragma unroll
    for (int i = 0; i < 8; i++) {
        int m = m0 + ty * 8 + i;
        if (m >= m_hi) continue;
        size_t base = (size_t)m * N + n0 + tx * 8;
#pragma unroll
        for (int h = 0; h < 2; h++) {
            float4 v = make_float4(lo32(acc2[i][2 * h]), hi32(acc2[i][2 * h]),
                                   lo32(acc2[i][2 * h + 1]), hi32(acc2[i][2 * h + 1]));
            if (EPI == 1) {
                float4 g = *(const float4*)(Gbuf + base + 4 * h);
                v.x *= g.x / (1.f + expf(-g.x));
                v.y *= g.y / (1.f + expf(-g.y));
                v.z *= g.z / (1.f + expf(-g.z));
                v.w *= g.w / (1.f + expf(-g.w));
            }
            *(float4*)(C + base + 4 * h) = v;
        }
    }
}

// ---------------- combine: out = shared + w0*pair[slot0] + w1*pair[slot1] ----------------
__global__ void k_combine(float* __restrict__ out, const float* __restrict__ pair, int T) {
    int t = blockIdx.x;
    float w0 = g_tw[2 * t], w1 = g_tw[2 * t + 1];
    size_t p0 = (size_t)g_slot[2 * t] * DIM;
    size_t p1 = (size_t)g_slot[2 * t + 1] * DIM;
    size_t ob = (size_t)t * DIM;
    for (int d = threadIdx.x * 4; d < DIM; d += blockDim.x * 4) {
        float4 a = *(const float4*)(pair + p0 + d);
        float4 b = *(const float4*)(pair + p1 + d);
        float4 o = *(const float4*)(out + ob + d);
        o.x += w0 * a.x + w1 * b.x;
        o.y += w0 * a.y + w1 * b.y;
        o.z += w0 * a.z + w1 * b.z;
        o.w += w0 * a.w + w1 * b.w;
        *(float4*)(out + ob + d) = o;
    }
}

// ---------------- launch ----------------
extern "C" void kernel_launch(void* const* d_in, const int* in_sizes, int n_in,
                              void* d_out, int out_size) {
    const float* x  = (const float*)d_in[0];
    const float* gw = (const float*)d_in[1];
    const float* sg = (const float*)d_in[2];
    const float* su = (const float*)d_in[3];
    const float* sd = (const float*)d_in[4];
    const float* eg = (const float*)d_in[5];
    const float* eu = (const float*)d_in[6];
    const float* ed = (const float*)d_in[7];
    float* out = (float*)d_out;

    int T = in_sizes[0] / DIM;       // 8192
    int A2 = 2 * T;                  // total assignments

    float *pG, *pPair;
    int *pAssign, *pOff;
    cudaGetSymbolAddress((void**)&pG, g_G);
    cudaGetSymbolAddress((void**)&pPair, g_pair);
    cudaGetSymbolAddress((void**)&pAssign, g_assign);
    cudaGetSymbolAddress((void**)&pOff, g_off);

    k_init<<<1, 32>>>();
    k_router<<<(T + 7) / 8, 256>>>(x, gw, T);
    k_scan<<<1, 1>>>(out, T, (size_t)out_size > (size_t)T * DIM ? 1 : 0);
    k_scatter<<<(T + 255) / 256, 256>>>(T);

    // shared expert: G = x@Wg ; H = silu(G)*(x@Wu) ; out = H@Wd
    k_gemm<0><<<dim3(IDIM / 128, T / 128, 1), 256>>>(x, sg, pG, nullptr, nullptr, T, IDIM, DIM, 0, nullptr);
    k_gemm<1><<<dim3(IDIM / 128, T / 128, 1), 256>>>(x, su, pG, nullptr, nullptr, T, IDIM, DIM, 0, pG);
    k_gemm<0><<<dim3(DIM / 128, T / 128, 1), 256>>>(pG, sd, out, nullptr, nullptr, T, DIM, IDIM, 0, nullptr);

    // routed experts (gathered rows, per-expert weights, worst-case grid.y; empty tiles exit)
    int mt = (A2 + 127) / 128;
    k_gemm<0><<<dim3(IDIM / 128, mt, NE), 256>>>(x, eg, pG, pAssign, pOff, A2, IDIM, DIM, (long)DIM * IDIM, nullptr);
    k_gemm<1><<<dim3(IDIM / 128, mt, NE), 256>>>(x, eu, pG, pAssign, pOff, A2, IDIM, DIM, (long)DIM * IDIM, pG);
    k_gemm<0><<<dim3(DIM / 128, mt, NE), 256>>>(pG, ed, pPair, nullptr, pOff, A2, DIM, IDIM, (long)IDIM * DIM, nullptr);

    k_combine<<<T, 256>>>(out, pPair, T);
}

// round 3
// speedup vs baseline: 1.5302x; 1.4427x over previous
#include <cuda_runtime.h>
#include <cuda_bf16.h>
#include <math.h>

#define NE 8
#define DIM 1024
#define IDIM 2048
#define TKN_MAX 8192
#define ASG_MAX 16384

typedef __nv_bfloat16 bf16;

// ---------------- device scratch (no allocs allowed) ----------------
__device__ float g_G[(size_t)ASG_MAX * IDIM];      // fp32 gate-proj intermediate
__device__ float g_pair[(size_t)ASG_MAX * DIM];    // per-assignment routed output
__device__ bf16  g_Hhi[(size_t)ASG_MAX * IDIM];    // swiglu output hi/lo
__device__ bf16  g_Hlo[(size_t)ASG_MAX * IDIM];
__device__ bf16  g_xhi[(size_t)TKN_MAX * DIM];
__device__ bf16  g_xlo[(size_t)TKN_MAX * DIM];
__device__ bf16  g_sghi[DIM * IDIM], g_sglo[DIM * IDIM];
__device__ bf16  g_suhi[DIM * IDIM], g_sulo[DIM * IDIM];
__device__ bf16  g_sdhi[IDIM * DIM], g_sdlo[IDIM * DIM];
__device__ bf16  g_eghi[(size_t)NE * DIM * IDIM], g_eglo[(size_t)NE * DIM * IDIM];
__device__ bf16  g_euhi[(size_t)NE * DIM * IDIM], g_eulo[(size_t)NE * DIM * IDIM];
__device__ bf16  g_edhi[(size_t)NE * IDIM * DIM], g_edlo[(size_t)NE * IDIM * DIM];
__device__ int   g_assign[ASG_MAX];
__device__ int   g_te[ASG_MAX];
__device__ float g_tw[ASG_MAX];
__device__ int   g_slot[ASG_MAX];
__device__ int   g_counts[NE];
__device__ int   g_off[NE + 1];
__device__ int   g_cursor[NE];
__device__ float g_psum[NE];

// ---------------- mma / ldmatrix helpers ----------------
__device__ __forceinline__ void mma_bf16(float* d, const unsigned* a, const unsigned* b) {
    asm volatile("mma.sync.aligned.m16n8k16.row.col.f32.bf16.bf16.f32 "
                 "{%0,%1,%2,%3}, {%4,%5,%6,%7}, {%8,%9}, {%0,%1,%2,%3};"
                 : "+f"(d[0]), "+f"(d[1]), "+f"(d[2]), "+f"(d[3])
                 : "r"(a[0]), "r"(a[1]), "r"(a[2]), "r"(a[3]), "r"(b[0]), "r"(b[1]));
}
__device__ __forceinline__ void ldsm4(unsigned* r, unsigned addr) {
    asm volatile("ldmatrix.sync.aligned.m8n8.x4.shared.b16 {%0,%1,%2,%3}, [%4];"
                 : "=r"(r[0]), "=r"(r[1]), "=r"(r[2]), "=r"(r[3]) : "r"(addr));
}
__device__ __forceinline__ void ldsm4t(unsigned* r, unsigned addr) {
    asm volatile("ldmatrix.sync.aligned.m8n8.x4.trans.shared.b16 {%0,%1,%2,%3}, [%4];"
                 : "=r"(r[0]), "=r"(r[1]), "=r"(r[2]), "=r"(r[3]) : "r"(addr));
}
__device__ __forceinline__ float silu_f(float x) { return x / (1.f + expf(-x)); }

// ---------------- init ----------------
__global__ void k_init() {
    int i = threadIdx.x;
    if (i < NE) { g_counts[i] = 0; g_psum[i] = 0.f; }
}

// ---------------- split: fp32 -> bf16 hi + bf16 lo ----------------
__global__ void k_split(const float4* __restrict__ in, __nv_bfloat162* __restrict__ hi,
                        __nv_bfloat162* __restrict__ lo, int n4) {
    int i = blockIdx.x * blockDim.x + threadIdx.x;
    if (i < n4) {
        float4 v = in[i];
        bf16 h0 = __float2bfloat16(v.x), h1 = __float2bfloat16(v.y);
        bf16 h2 = __float2bfloat16(v.z), h3 = __float2bfloat16(v.w);
        bf16 l0 = __float2bfloat16(v.x - __bfloat162float(h0));
        bf16 l1 = __float2bfloat16(v.y - __bfloat162float(h1));
        bf16 l2 = __float2bfloat16(v.z - __bfloat162float(h2));
        bf16 l3 = __float2bfloat16(v.w - __bfloat162float(h3));
        hi[2 * i]     = __nv_bfloat162(h0, h1);
        hi[2 * i + 1] = __nv_bfloat162(h2, h3);
        lo[2 * i]     = __nv_bfloat162(l0, l1);
        lo[2 * i + 1] = __nv_bfloat162(l2, l3);
    }
}

// ---------------- router ----------------
__global__ void k_router(const float* __restrict__ x, const float* __restrict__ gw, int T) {
    __shared__ float sP[NE];
    if (threadIdx.x < NE) sP[threadIdx.x] = 0.f;
    __syncthreads();

    int warp = (blockIdx.x * blockDim.x + threadIdx.x) >> 5;
    int lane = threadIdx.x & 31;
    if (warp < T) {
        const float* xr = x + (size_t)warp * DIM;
        float acc[NE];
#pragma unroll
        for (int e = 0; e < NE; e++) acc[e] = 0.f;
        for (int i = lane; i < DIM; i += 32) {
            float xv = xr[i];
#pragma unroll
            for (int e = 0; e < NE; e++) acc[e] = fmaf(xv, gw[e * DIM + i], acc[e]);
        }
#pragma unroll
        for (int e = 0; e < NE; e++) {
#pragma unroll
            for (int o = 16; o; o >>= 1) acc[e] += __shfl_xor_sync(0xffffffffu, acc[e], o);
        }
        if (lane == 0) {
            float mx = acc[0];
#pragma unroll
            for (int e = 1; e < NE; e++) mx = fmaxf(mx, acc[e]);
            float ex[NE]; float s = 0.f;
#pragma unroll
            for (int e = 0; e < NE; e++) { ex[e] = expf(acc[e] - mx); s += ex[e]; }
            float inv = 1.f / s;
#pragma unroll
            for (int e = 0; e < NE; e++) atomicAdd(&sP[e], ex[e] * inv);
            int i0 = 0;
#pragma unroll
            for (int e = 1; e < NE; e++) if (acc[e] > acc[i0]) i0 = e;
            int i1 = (i0 == 0) ? 1 : 0;
#pragma unroll
            for (int e = 0; e < NE; e++) if (e != i0 && acc[e] > acc[i1]) i1 = e;
            float m2 = fmaxf(acc[i0], acc[i1]);
            float e0 = expf(acc[i0] - m2), e1 = expf(acc[i1] - m2);
            float wsum = e0 + e1;
            g_te[2 * warp] = i0; g_te[2 * warp + 1] = i1;
            g_tw[2 * warp] = e0 / wsum; g_tw[2 * warp + 1] = e1 / wsum;
            atomicAdd(&g_counts[i0], 1);
            atomicAdd(&g_counts[i1], 1);
        }
    }
    __syncthreads();
    if (threadIdx.x < NE) atomicAdd(&g_psum[threadIdx.x], sP[threadIdx.x]);
}

// ---------------- scan ----------------
__global__ void k_scan(float* __restrict__ out, int T, int write_aux) {
    if (threadIdx.x == 0 && blockIdx.x == 0) {
        int o = 0;
        float aux = 0.f;
        for (int e = 0; e < NE; e++) {
            g_off[e] = o; g_cursor[e] = o;
            float f = (float)g_counts[e] / (float)(T * 2);
            float P = g_psum[e] / (float)T;
            aux += f * P;
            o += g_counts[e];
        }
        g_off[NE] = o;
        if (write_aux) out[(size_t)T * DIM] = (float)NE * aux;
    }
}

// ---------------- scatter ----------------
__global__ void k_scatter(int T) {
    int t = blockIdx.x * blockDim.x + threadIdx.x;
    if (t < T) {
#pragma unroll
        for (int k = 0; k < 2; k++) {
            int e = g_te[2 * t + k];
            int pos = atomicAdd(&g_cursor[e], 1);
            g_assign[pos] = t;
            g_slot[2 * t + k] = pos;
        }
    }
}

// ---------------- bf16x3 tensor-core GEMM ----------------
// C[m, n-tile] = A[rid(m), :K] @ B[:, n-tile], error-compensated bf16 split.
// EPI==0: write fp32 C.  EPI==1: h = silu(Gbuf)*acc; write bf16 hi/lo (Hhi/Hlo).
template <int EPI>
__global__ __launch_bounds__(256) void k_gemm(
    const bf16* __restrict__ Ahi_g, const bf16* __restrict__ Alo_g,
    const bf16* __restrict__ Bhi_g, const bf16* __restrict__ Blo_g,
    float* __restrict__ C, const float* __restrict__ Gbuf,
    bf16* __restrict__ Hhi_g, bf16* __restrict__ Hlo_g,
    const int* __restrict__ row_ids, const int* __restrict__ seg_off,
    int M, int N, int K, long strideB)
{
    int m_lo = 0, m_hi = M;
    long segB = 0;
    if (seg_off) {
        int s = blockIdx.z;
        m_lo = seg_off[s]; m_hi = seg_off[s + 1];
        segB = (long)s * strideB;
    }
    int m0 = m_lo + blockIdx.y * 128;
    if (m0 >= m_hi) return;
    int n0 = blockIdx.x * 128;

    __shared__ __align__(16) bf16 Ahi_s[128][56];
    __shared__ __align__(16) bf16 Alo_s[128][56];
    __shared__ __align__(16) bf16 Bhi_s[32][136];
    __shared__ __align__(16) bf16 Blo_s[32][136];

    int tid = threadIdx.x;
    int lane = tid & 31;
    int warp = tid >> 5;
    int wm = warp >> 2;          // 0..1  (M)
    int wn = warp & 3;           // 0..3  (N)

    // ---- global-load addressing ----
    int arow = tid >> 2;                 // 0..63
    int acol = (tid & 3) << 3;           // 0,8,16,24
    int gm0 = m0 + arow; if (gm0 > M - 1) gm0 = M - 1;
    int gm1 = m0 + arow + 64; if (gm1 > M - 1) gm1 = M - 1;
    int rid0 = row_ids ? row_ids[gm0] : gm0;
    int rid1 = row_ids ? row_ids[gm1] : gm1;
    const bf16* pAh0 = Ahi_g + (size_t)rid0 * K + acol;
    const bf16* pAh1 = Ahi_g + (size_t)rid1 * K + acol;
    const bf16* pAl0 = Alo_g + (size_t)rid0 * K + acol;
    const bf16* pAl1 = Alo_g + (size_t)rid1 * K + acol;

    int brow = tid >> 4;                 // 0..15
    int bcol = (tid & 15) << 3;          // 0..120
    const bf16* pBh0 = Bhi_g + segB + (size_t)brow * N + n0 + bcol;
    const bf16* pBh1 = pBh0 + (size_t)16 * N;
    const bf16* pBl0 = Blo_g + segB + (size_t)brow * N + n0 + bcol;
    const bf16* pBl1 = pBl0 + (size_t)16 * N;

    // ---- accumulators ----
    float acc[4][4][4];
#pragma unroll
    for (int i = 0; i < 4; i++)
#pragma unroll
        for (int j = 0; j < 4; j++)
#pragma unroll
            for (int r = 0; r < 4; r++) acc[i][j][r] = 0.f;

    // ---- ldmatrix smem addresses (byte offsets precomputed per lane) ----
    unsigned sAhi = (unsigned)__cvta_generic_to_shared(&Ahi_s[0][0]);
    unsigned sAlo = (unsigned)__cvta_generic_to_shared(&Alo_s[0][0]);
    unsigned sBhi = (unsigned)__cvta_generic_to_shared(&Bhi_s[0][0]);
    unsigned sBlo = (unsigned)__cvta_generic_to_shared(&Blo_s[0][0]);
    int laneA = ((lane & 15) * 56 + ((lane >> 4) << 3)) * 2;   // + (row)*112 + koff*2
    int laneBr = (lane & 15) * 136 * 2;
    int laneBc = ((lane >> 4) << 3) * 2;

    // ---- prologue prefetch ----
    uint4 vah0 = *(const uint4*)(pAh0);
    uint4 vah1 = *(const uint4*)(pAh1);
    uint4 val0 = *(const uint4*)(pAl0);
    uint4 val1 = *(const uint4*)(pAl1);
    uint4 vbh0 = *(const uint4*)(pBh0);
    uint4 vbh1 = *(const uint4*)(pBh1);
    uint4 vbl0 = *(const uint4*)(pBl0);
    uint4 vbl1 = *(const uint4*)(pBl1);

    for (int k0 = 0; k0 < K; k0 += 32) {
        *(uint4*)&Ahi_s[arow][acol] = vah0;
        *(uint4*)&Ahi_s[arow + 64][acol] = vah1;
        *(uint4*)&Alo_s[arow][acol] = val0;
        *(uint4*)&Alo_s[arow + 64][acol] = val1;
        *(uint4*)&Bhi_s[brow][bcol] = vbh0;
        *(uint4*)&Bhi_s[brow + 16][bcol] = vbh1;
        *(uint4*)&Blo_s[brow][bcol] = vbl0;
        *(uint4*)&Blo_s[brow + 16][bcol] = vbl1;
        __syncthreads();

        if (k0 + 32 < K) {
            int kn = k0 + 32;
            vah0 = *(const uint4*)(pAh0 + kn);
            vah1 = *(const uint4*)(pAh1 + kn);
            val0 = *(const uint4*)(pAl0 + kn);
            val1 = *(const uint4*)(pAl1 + kn);
            long bo = (long)kn * N;
            vbh0 = *(const uint4*)(pBh0 + bo);
            vbh1 = *(const uint4*)(pBh1 + bo);
            vbl0 = *(const uint4*)(pBl0 + bo);
            vbl1 = *(const uint4*)(pBl1 + bo);
        }

#pragma unroll
        for (int ks = 0; ks < 2; ks++) {
            // B fragments: 2x ldsm4t per buffer covers n16 each -> 4 n8 frags
            unsigned bfh[4][2], bfl[4][2];
#pragma unroll
            for (int ni2 = 0; ni2 < 2; ni2++) {
                unsigned baddr = (ks * 16) * 136 * 2 + laneBr + (wn * 32 + ni2 * 16) * 2 + laneBc;
                unsigned t[4];
                ldsm4t(t, sBhi + baddr);
                bfh[2 * ni2][0] = t[0]; bfh[2 * ni2][1] = t[1];
                bfh[2 * ni2 + 1][0] = t[2]; bfh[2 * ni2 + 1][1] = t[3];
                ldsm4t(t, sBlo + baddr);
                bfl[2 * ni2][0] = t[0]; bfl[2 * ni2][1] = t[1];
                bfl[2 * ni2 + 1][0] = t[2]; bfl[2 * ni2 + 1][1] = t[3];
            }
#pragma unroll
            for (int mi = 0; mi < 4; mi++) {
                unsigned aaddr = (wm * 64 + mi * 16) * 56 * 2 + laneA + (ks * 16) * 2;
                unsigned ah[4], al[4];
                ldsm4(ah, sAhi + aaddr);
                ldsm4(al, sAlo + aaddr);
#pragma unroll
                for (int ni = 0; ni < 4; ni++) {
                    mma_bf16(acc[mi][ni], ah, bfh[ni]);   // hi*hi
                    mma_bf16(acc[mi][ni], al, bfh[ni]);   // lo*hi
                    mma_bf16(acc[mi][ni], ah, bfl[ni]);   // hi*lo
                }
            }
        }
        __syncthreads();
    }

    // ---- epilogue ----
    int mrow = m0 + wm * 64 + (lane >> 2);
    int mcol = n0 + wn * 32 + ((lane & 3) << 1);
#pragma unroll
    for (int mi = 0; mi < 4; mi++) {
#pragma unroll
        for (int half = 0; half < 2; half++) {
            int r = mrow + mi * 16 + half * 8;
            if (r >= m_hi) continue;
#pragma unroll
            for (int ni = 0; ni < 4; ni++) {
                int c = mcol + ni * 8;
                size_t idx = (size_t)r * N + c;
                float v0 = acc[mi][ni][2 * half];
                float v1 = acc[mi][ni][2 * half + 1];
                if (EPI == 0) {
                    *(float2*)(C + idx) = make_float2(v0, v1);
                } else {
                    float2 g = *(const float2*)(Gbuf + idx);
                    float h0 = silu_f(g.x) * v0;
                    float h1 = silu_f(g.y) * v1;
                    bf16 hh0 = __float2bfloat16(h0);
                    bf16 hh1 = __float2bfloat16(h1);
                    bf16 hl0 = __float2bfloat16(h0 - __bfloat162float(hh0));
                    bf16 hl1 = __float2bfloat16(h1 - __bfloat162float(hh1));
                    *(__nv_bfloat162*)(Hhi_g + idx) = __nv_bfloat162(hh0, hh1);
                    *(__nv_bfloat162*)(Hlo_g + idx) = __nv_bfloat162(hl0, hl1);
                }
            }
        }
    }
}

// ---------------- combine ----------------
__global__ void k_combine(float* __restrict__ out, const float* __restrict__ pair, int T) {
    int t = blockIdx.x;
    float w0 = g_tw[2 * t], w1 = g_tw[2 * t + 1];
    size_t p0 = (size_t)g_slot[2 * t] * DIM;
    size_t p1 = (size_t)g_slot[2 * t + 1] * DIM;
    size_t ob = (size_t)t * DIM;
    for (int d = threadIdx.x * 4; d < DIM; d += blockDim.x * 4) {
        float4 a = *(const float4*)(pair + p0 + d);
        float4 b = *(const float4*)(pair + p1 + d);
        float4 o = *(const float4*)(out + ob + d);
        o.x += w0 * a.x + w1 * b.x;
        o.y += w0 * a.y + w1 * b.y;
        o.z += w0 * a.z + w1 * b.z;
        o.w += w0 * a.w + w1 * b.w;
        *(float4*)(out + ob + d) = o;
    }
}

// ---------------- launch ----------------
static void split_launch(const float* src, bf16* hi, bf16* lo, size_t n) {
    int n4 = (int)(n / 4);
    k_split<<<(n4 + 255) / 256, 256>>>((const float4*)src, (__nv_bfloat162*)hi,
                                       (__nv_bfloat162*)lo, n4);
}

extern "C" void kernel_launch(void* const* d_in, const int* in_sizes, int n_in,
                              void* d_out, int out_size) {
    const float* x  = (const float*)d_in[0];
    const float* gw = (const float*)d_in[1];
    const float* sg = (const float*)d_in[2];
    const float* su = (const float*)d_in[3];
    const float* sd = (const float*)d_in[4];
    const float* eg = (const float*)d_in[5];
    const float* eu = (const float*)d_in[6];
    const float* ed = (const float*)d_in[7];
    float* out = (float*)d_out;

    int T = in_sizes[0] / DIM;       // 8192
    int A2 = 2 * T;

    float *pG, *pPair;
    int *pAssign, *pOff;
    bf16 *pXhi, *pXlo, *pHhi, *pHlo;
    bf16 *pSGhi, *pSGlo, *pSUhi, *pSUlo, *pSDhi, *pSDlo;
    bf16 *pEGhi, *pEGlo, *pEUhi, *pEUlo, *pEDhi, *pEDlo;
    cudaGetSymbolAddress((void**)&pG, g_G);
    cudaGetSymbolAddress((void**)&pPair, g_pair);
    cudaGetSymbolAddress((void**)&pAssign, g_assign);
    cudaGetSymbolAddress((void**)&pOff, g_off);
    cudaGetSymbolAddress((void**)&pXhi, g_xhi);
    cudaGetSymbolAddress((void**)&pXlo, g_xlo);
    cudaGetSymbolAddress((void**)&pHhi, g_Hhi);
    cudaGetSymbolAddress((void**)&pHlo, g_Hlo);
    cudaGetSymbolAddress((void**)&pSGhi, g_sghi);
    cudaGetSymbolAddress((void**)&pSGlo, g_sglo);
    cudaGetSymbolAddress((void**)&pSUhi, g_suhi);
    cudaGetSymbolAddress((void**)&pSUlo, g_sulo);
    cudaGetSymbolAddress((void**)&pSDhi, g_sdhi);
    cudaGetSymbolAddress((void**)&pSDlo, g_sdlo);
    cudaGetSymbolAddress((void**)&pEGhi, g_eghi);
    cudaGetSymbolAddress((void**)&pEGlo, g_eglo);
    cudaGetSymbolAddress((void**)&pEUhi, g_euhi);
    cudaGetSymbolAddress((void**)&pEUlo, g_eulo);
    cudaGetSymbolAddress((void**)&pEDhi, g_edhi);
    cudaGetSymbolAddress((void**)&pEDlo, g_edlo);

    k_init<<<1, 32>>>();
    k_router<<<(T + 7) / 8, 256>>>(x, gw, T);
    k_scan<<<1, 1>>>(out, T, (size_t)out_size > (size_t)T * DIM ? 1 : 0);
    k_scatter<<<(T + 255) / 256, 256>>>(T);

    // fp32 -> bf16 hi/lo splits
    split_launch(x,  pXhi, pXlo, (size_t)T * DIM);
    split_launch(sg, pSGhi, pSGlo, (size_t)DIM * IDIM);
    split_launch(su, pSUhi, pSUlo, (size_t)DIM * IDIM);
    split_launch(sd, pSDhi, pSDlo, (size_t)IDIM * DIM);
    split_launch(eg, pEGhi, pEGlo, (size_t)NE * DIM * IDIM);
    split_launch(eu, pEUhi, pEUlo, (size_t)NE * DIM * IDIM);
    split_launch(ed, pEDhi, pEDlo, (size_t)NE * IDIM * DIM);

    // shared expert
    k_gemm<0><<<dim3(IDIM / 128, T / 128, 1), 256>>>(
        pXhi, pXlo, pSGhi, pSGlo, pG, nullptr, nullptr, nullptr,
        nullptr, nullptr, T, IDIM, DIM, 0);
    k_gemm<1><<<dim3(IDIM / 128, T / 128, 1), 256>>>(
        pXhi, pXlo, pSUhi, pSUlo, nullptr, pG, pHhi, pHlo,
        nullptr, nullptr, T, IDIM, DIM, 0);
    k_gemm<0><<<dim3(DIM / 128, T / 128, 1), 256>>>(
        pHhi, pHlo, pSDhi, pSDlo, out, nullptr, nullptr, nullptr,
        nullptr, nullptr, T, DIM, IDIM, 0);

    // routed experts
    int mt = (A2 + 127) / 128;
    k_gemm<0><<<dim3(IDIM / 128, mt, NE), 256>>>(
        pXhi, pXlo, pEGhi, pEGlo, pG, nullptr, nullptr, nullptr,
        pAssign, pOff, A2, IDIM, DIM, (long)DIM * IDIM);
    k_gemm<1><<<dim3(IDIM / 128, mt, NE), 256>>>(
        pXhi, pXlo, pEUhi, pEUlo, nullptr, pG, pHhi, pHlo,
        pAssign, pOff, A2, IDIM, DIM, (long)DIM * IDIM);
    k_gemm<0><<<dim3(DIM / 128, mt, NE), 256>>>(
        pHhi, pHlo, pEDhi, pEDlo, pPair, nullptr, nullptr, nullptr,
        nullptr, pOff, A2, DIM, IDIM, (long)IDIM * DIM);

    k_combine<<<T, 256>>>(out, pPair, T);
}

// round 7
// speedup vs baseline: 1.8679x; 1.2206x over previous
#include <cuda_runtime.h>
#include <cuda_bf16.h>
#include <cstdint>
#include <math.h>

#define NE 8
#define DIM 1024
#define IDIM 2048
#define TKN_MAX 8192
#define ASG_MAX 16384

typedef __nv_bfloat16 bf16;

// ---------------- device scratch (no allocs allowed) ----------------
__device__ float g_G[(size_t)ASG_MAX * IDIM];      // fp32 gate-proj intermediate
__device__ float g_pair[(size_t)ASG_MAX * DIM];    // per-assignment routed output
__device__ bf16  g_Hhi[(size_t)ASG_MAX * IDIM];    // swiglu output hi/lo
__device__ bf16  g_Hlo[(size_t)ASG_MAX * IDIM];
__device__ bf16  g_xhi[(size_t)TKN_MAX * DIM];     // x split (shared expert)
__device__ bf16  g_xlo[(size_t)TKN_MAX * DIM];
__device__ bf16  g_xghi[(size_t)ASG_MAX * DIM];    // gathered x split (routed)
__device__ bf16  g_xglo[(size_t)ASG_MAX * DIM];
// transposed weights [N, K] hi/lo
__device__ bf16  g_sgThi[(size_t)IDIM * DIM], g_sgTlo[(size_t)IDIM * DIM];
__device__ bf16  g_suThi[(size_t)IDIM * DIM], g_suTlo[(size_t)IDIM * DIM];
__device__ bf16  g_sdThi[(size_t)DIM * IDIM], g_sdTlo[(size_t)DIM * IDIM];
__device__ bf16  g_egThi[(size_t)NE * IDIM * DIM], g_egTlo[(size_t)NE * IDIM * DIM];
__device__ bf16  g_euThi[(size_t)NE * IDIM * DIM], g_euTlo[(size_t)NE * IDIM * DIM];
__device__ bf16  g_edThi[(size_t)NE * DIM * IDIM], g_edTlo[(size_t)NE * DIM * IDIM];
__device__ int   g_assign[ASG_MAX];
__device__ int   g_te[ASG_MAX];
__device__ float g_tw[ASG_MAX];
__device__ int   g_slot[ASG_MAX];
__device__ int   g_counts[NE];
__device__ int   g_off[NE + 1];
__device__ int   g_cursor[NE];
__device__ float g_psum[NE];

// ---------------- mma / ldmatrix / cp.async helpers ----------------
__device__ __forceinline__ void mma_bf16(float* d, const unsigned* a, const unsigned* b) {
    asm volatile("mma.sync.aligned.m16n8k16.row.col.f32.bf16.bf16.f32 "
                 "{%0,%1,%2,%3}, {%4,%5,%6,%7}, {%8,%9}, {%0,%1,%2,%3};"
                 : "+f"(d[0]), "+f"(d[1]), "+f"(d[2]), "+f"(d[3])
                 : "r"(a[0]), "r"(a[1]), "r"(a[2]), "r"(a[3]), "r"(b[0]), "r"(b[1]));
}
__device__ __forceinline__ void ldsm4(unsigned* r, unsigned addr) {
    asm volatile("ldmatrix.sync.aligned.m8n8.x4.shared.b16 {%0,%1,%2,%3}, [%4];"
                 : "=r"(r[0]), "=r"(r[1]), "=r"(r[2]), "=r"(r[3]) : "r"(addr));
}
#define CPA16(dst, src) \
    asm volatile("cp.async.cg.shared.global [%0], [%1], 16;" :: "r"(dst), "l"(src))
#define CP_COMMIT() asm volatile("cp.async.commit_group;" ::: "memory")
#define CP_WAIT1()  asm volatile("cp.async.wait_group 1;" ::: "memory")

__device__ __forceinline__ float silu_f(float x) { return x / (1.f + expf(-x)); }

// ---------------- init ----------------
__global__ void k_init() {
    int i = threadIdx.x;
    if (i < NE) { g_counts[i] = 0; g_psum[i] = 0.f; }
}

// ---------------- split: fp32 -> bf16 hi + bf16 lo ----------------
__global__ void k_split(const float4* __restrict__ in, __nv_bfloat162* __restrict__ hi,
                        __nv_bfloat162* __restrict__ lo, int n4) {
    int i = blockIdx.x * blockDim.x + threadIdx.x;
    if (i < n4) {
        float4 v = in[i];
        bf16 h0 = __float2bfloat16(v.x), h1 = __float2bfloat16(v.y);
        bf16 h2 = __float2bfloat16(v.z), h3 = __float2bfloat16(v.w);
        bf16 l0 = __float2bfloat16(v.x - __bfloat162float(h0));
        bf16 l1 = __float2bfloat16(v.y - __bfloat162float(h1));
        bf16 l2 = __float2bfloat16(v.z - __bfloat162float(h2));
        bf16 l3 = __float2bfloat16(v.w - __bfloat162float(h3));
        hi[2 * i]     = __nv_bfloat162(h0, h1);
        hi[2 * i + 1] = __nv_bfloat162(h2, h3);
        lo[2 * i]     = __nv_bfloat162(l0, l1);
        lo[2 * i + 1] = __nv_bfloat162(l2, l3);
    }
}

// ---------------- transpose + split: W[K,N] fp32 -> Wt[N,K] bf16 hi/lo ----------------
__global__ void k_tsplit(const float* __restrict__ W, bf16* __restrict__ hi,
                         bf16* __restrict__ lo, int K, int N) {
    __shared__ float t[32][33];
    size_t eo = (size_t)blockIdx.z * K * N;
    int k0 = blockIdx.y * 32, n0 = blockIdx.x * 32;
    int tx = threadIdx.x & 31, ty = threadIdx.x >> 5;
#pragma unroll
    for (int r = ty; r < 32; r += 8)
        t[r][tx] = W[eo + (size_t)(k0 + r) * N + n0 + tx];
    __syncthreads();
#pragma unroll
    for (int r = ty; r < 32; r += 8) {
        float v = t[tx][r];
        bf16 h = __float2bfloat16(v);
        bf16 l = __float2bfloat16(v - __bfloat162float(h));
        size_t o = eo + (size_t)(n0 + r) * K + k0 + tx;
        hi[o] = h; lo[o] = l;
    }
}

// ---------------- gather + split ----------------
__global__ void k_gsplit(const float* __restrict__ x, __nv_bfloat162* __restrict__ hi,
                         __nv_bfloat162* __restrict__ lo) {
    int a = blockIdx.x;
    int t = g_assign[a];
    const float4* src = (const float4*)(x + (size_t)t * DIM);
    int i = threadIdx.x;                 // 256 threads, DIM/4 = 256
    float4 v = src[i];
    bf16 h0 = __float2bfloat16(v.x), h1 = __float2bfloat16(v.y);
    bf16 h2 = __float2bfloat16(v.z), h3 = __float2bfloat16(v.w);
    bf16 l0 = __float2bfloat16(v.x - __bfloat162float(h0));
    bf16 l1 = __float2bfloat16(v.y - __bfloat162float(h1));
    bf16 l2 = __float2bfloat16(v.z - __bfloat162float(h2));
    bf16 l3 = __float2bfloat16(v.w - __bfloat162float(h3));
    size_t o = (size_t)a * (DIM / 2) + 2 * i;
    hi[o]     = __nv_bfloat162(h0, h1);
    hi[o + 1] = __nv_bfloat162(h2, h3);
    lo[o]     = __nv_bfloat162(l0, l1);
    lo[o + 1] = __nv_bfloat162(l2, l3);
}

// ---------------- router ----------------
__global__ void k_router(const float* __restrict__ x, const float* __restrict__ gw, int T) {
    __shared__ float sP[NE];
    if (threadIdx.x < NE) sP[threadIdx.x] = 0.f;
    __syncthreads();

    int warp = (blockIdx.x * blockDim.x + threadIdx.x) >> 5;
    int lane = threadIdx.x & 31;
    if (warp < T) {
        const float* xr = x + (size_t)warp * DIM;
        float acc[NE];
#pragma unroll
        for (int e = 0; e < NE; e++) acc[e] = 0.f;
        for (int i = lane; i < DIM; i += 32) {
            float xv = xr[i];
#pragma unroll
            for (int e = 0; e < NE; e++) acc[e] = fmaf(xv, gw[e * DIM + i], acc[e]);
        }
#pragma unroll
        for (int e = 0; e < NE; e++) {
#pragma unroll
            for (int o = 16; o; o >>= 1) acc[e] += __shfl_xor_sync(0xffffffffu, acc[e], o);
        }
        if (lane == 0) {
            float mx = acc[0];
#pragma unroll
            for (int e = 1; e < NE; e++) mx = fmaxf(mx, acc[e]);
            float ex[NE]; float s = 0.f;
#pragma unroll
            for (int e = 0; e < NE; e++) { ex[e] = expf(acc[e] - mx); s += ex[e]; }
            float inv = 1.f / s;
#pragma unroll
            for (int e = 0; e < NE; e++) atomicAdd(&sP[e], ex[e] * inv);
            int i0 = 0;
#pragma unroll
            for (int e = 1; e < NE; e++) if (acc[e] > acc[i0]) i0 = e;
            int i1 = (i0 == 0) ? 1 : 0;
#pragma unroll
            for (int e = 0; e < NE; e++) if (e != i0 && acc[e] > acc[i1]) i1 = e;
            float m2 = fmaxf(acc[i0], acc[i1]);
            float e0 = expf(acc[i0] - m2), e1 = expf(acc[i1] - m2);
            float wsum = e0 + e1;
            g_te[2 * warp] = i0; g_te[2 * warp + 1] = i1;
            g_tw[2 * warp] = e0 / wsum; g_tw[2 * warp + 1] = e1 / wsum;
            atomicAdd(&g_counts[i0], 1);
            atomicAdd(&g_counts[i1], 1);
        }
    }
    __syncthreads();
    if (threadIdx.x < NE) atomicAdd(&g_psum[threadIdx.x], sP[threadIdx.x]);
}

// ---------------- scan ----------------
__global__ void k_scan(float* __restrict__ out, int T, int write_aux) {
    if (threadIdx.x == 0 && blockIdx.x == 0) {
        int o = 0;
        float aux = 0.f;
        for (int e = 0; e < NE; e++) {
            g_off[e] = o; g_cursor[e] = o;
            float f = (float)g_counts[e] / (float)(T * 2);
            float P = g_psum[e] / (float)T;
            aux += f * P;
            o += g_counts[e];
        }
        g_off[NE] = o;
        if (write_aux) out[(size_t)T * DIM] = (float)NE * aux;
    }
}

// ---------------- scatter ----------------
__global__ void k_scatter(int T) {
    int t = blockIdx.x * blockDim.x + threadIdx.x;
    if (t < T) {
#pragma unroll
        for (int k = 0; k < 2; k++) {
            int e = g_te[2 * t + k];
            int pos = atomicAdd(&g_cursor[e], 1);
            g_assign[pos] = t;
            g_slot[2 * t + k] = pos;
        }
    }
}

// ---------------- pipelined bf16x3 HMMA GEMM ----------------
// C[128,128] tile: C[m,n] = sum_k A[m,k]*Bt[n,k]; A,Bt bf16 hi/lo (both K-major).
// 3-stage cp.async; stride-40 smem rows (bank-conflict-free ldmatrix).
// EPI==0: fp32 C.  EPI==1: h = silu(Gbuf)*acc -> bf16 hi/lo (Hhi/Hlo).
#define BK 32
#define STG 3
#define RSTRIDE 40                       // smem row stride in elements
#define TILE_E (128 * RSTRIDE)           // 5120 elems per tile
#define STAGE_E (4 * TILE_E)             // Ahi, Alo, Bhi, Blo
#define GEMM_SMEM (STG * STAGE_E * 2)    // bytes = 122880

template <int EPI>
__global__ __launch_bounds__(256) void k_gemm_p(
    const bf16* __restrict__ Ahi, const bf16* __restrict__ Alo,
    const bf16* __restrict__ BhiT, const bf16* __restrict__ BloT,
    float* __restrict__ C, const float* __restrict__ Gbuf,
    bf16* __restrict__ Hhi, bf16* __restrict__ Hlo,
    const int* __restrict__ seg_off,
    int M, int N, int K, long strideB, int NST)
{
    int m_lo = 0, m_hi = M;
    const bf16* Bh = BhiT;
    const bf16* Bl = BloT;
    if (seg_off) {
        int s = blockIdx.z;
        m_lo = seg_off[s]; m_hi = seg_off[s + 1];
        Bh += (size_t)s * strideB;
        Bl += (size_t)s * strideB;
    }
    int m0 = m_lo + blockIdx.y * 128;
    if (m0 >= m_hi) return;
    int n0 = blockIdx.x * 128;

    extern __shared__ __align__(16) bf16 sm[];
    int tid = threadIdx.x, lane = tid & 31, wid = tid >> 5;
    int wm = wid >> 2, wn = wid & 3;

    // ---- per-thread load addressing: row r = tid>>1, 16-elem half h = tid&1 ----
    int lr = tid >> 1, lh = tid & 1;
    int gr = m0 + lr; if (gr > M - 1) gr = M - 1;
    int gn = n0 + lr;
    const char* pAh = (const char*)(Ahi + (size_t)gr * K + lh * 16);
    const char* pAl = (const char*)(Alo + (size_t)gr * K + lh * 16);
    const char* pBh = (const char*)(Bh + (size_t)gn * K + lh * 16);
    const char* pBl = (const char*)(Bl + (size_t)gn * K + lh * 16);
    unsigned sdst;
    {
        unsigned sb;
        asm("{ .reg .u64 t; cvta.to.shared.u64 t, %1; cvt.u32.u64 %0, t; }"
            : "=r"(sb) : "l"(sm));
        sdst = sb + (unsigned)(lr * RSTRIDE + lh * 16) * 2;
    }

    auto load_stage = [&](int stage, int buf) {
        unsigned d = sdst + (unsigned)buf * (STAGE_E * 2);
        long go = (long)stage * BK * 2;            // byte advance along K
#pragma unroll
        for (int c = 0; c < 2; c++) {
            CPA16(d + c * 16,                    pAh + go + c * 16);
            CPA16(d + TILE_E * 2 + c * 16,       pAl + go + c * 16);
            CPA16(d + TILE_E * 4 + c * 16,       pBh + go + c * 16);
            CPA16(d + TILE_E * 6 + c * 16,       pBl + go + c * 16);
        }
    };

    // ---- accumulators ----
    float acc[4][4][4];
#pragma unroll
    for (int i = 0; i < 4; i++)
#pragma unroll
        for (int j = 0; j < 4; j++)
#pragma unroll
            for (int r = 0; r < 4; r++) acc[i][j][r] = 0.f;

    // ---- ldmatrix lane offset (within a tile): row lane&15, koff (lane>>4)*8 ----
    unsigned sbase;
    asm("{ .reg .u64 t; cvta.to.shared.u64 t, %1; cvt.u32.u64 %0, t; }"
        : "=r"(sbase) : "l"(sm));
    unsigned laneOff = (unsigned)(((lane & 15) * RSTRIDE + ((lane >> 4) << 3)) * 2);

    // ---- prologue ----
#pragma unroll
    for (int s = 0; s < STG - 1; s++) {
        if (s < NST) load_stage(s, s);
        CP_COMMIT();
    }

    for (int i = 0; i < NST; i++) {
        CP_WAIT1();
        __syncthreads();
        if (i + STG - 1 < NST) load_stage(i + STG - 1, (i + STG - 1) % STG);
        CP_COMMIT();

        int buf = i % STG;
        unsigned tb = sbase + (unsigned)buf * (STAGE_E * 2);
        unsigned tAh = tb + laneOff;
        unsigned tAl = tb + TILE_E * 2 + laneOff;
        unsigned tBh = tb + TILE_E * 4 + laneOff;
        unsigned tBl = tb + TILE_E * 6 + laneOff;

#pragma unroll
        for (int ks = 0; ks < 2; ks++) {
            unsigned kb = (unsigned)(ks * 16 * 2);
            unsigned bh[4][2], bl[4][2];
#pragma unroll
            for (int nb = 0; nb < 2; nb++) {
                unsigned roff = (unsigned)((wn * 32 + nb * 16) * RSTRIDE * 2) + kb;
                unsigned t[4];
                ldsm4(t, tBh + roff);
                bh[2 * nb][0] = t[0]; bh[2 * nb][1] = t[2];
                bh[2 * nb + 1][0] = t[1]; bh[2 * nb + 1][1] = t[3];
                ldsm4(t, tBl + roff);
                bl[2 * nb][0] = t[0]; bl[2 * nb][1] = t[2];
                bl[2 * nb + 1][0] = t[1]; bl[2 * nb + 1][1] = t[3];
            }
#pragma unroll
            for (int mi = 0; mi < 4; mi++) {
                unsigned roff = (unsigned)((wm * 64 + mi * 16) * RSTRIDE * 2) + kb;
                unsigned ah[4], al[4];
                ldsm4(ah, tAh + roff);
                ldsm4(al, tAl + roff);
#pragma unroll
                for (int ni = 0; ni < 4; ni++) mma_bf16(acc[mi][ni], ah, bh[ni]);
#pragma unroll
                for (int ni = 0; ni < 4; ni++) mma_bf16(acc[mi][ni], al, bh[ni]);
#pragma unroll
                for (int ni = 0; ni < 4; ni++) mma_bf16(acc[mi][ni], ah, bl[ni]);
            }
        }
        __syncthreads();
    }

    // ---- epilogue ----
    int mrow = m0 + wm * 64 + (lane >> 2);
    int mcol = n0 + wn * 32 + ((lane & 3) << 1);
#pragma unroll
    for (int mi = 0; mi < 4; mi++) {
#pragma unroll
        for (int half = 0; half < 2; half++) {
            int r = mrow + mi * 16 + half * 8;
            if (r >= m_hi) continue;
#pragma unroll
            for (int ni = 0; ni < 4; ni++) {
                int c = mcol + ni * 8;
                size_t idx = (size_t)r * N + c;
                float v0 = acc[mi][ni][2 * half];
                float v1 = acc[mi][ni][2 * half + 1];
                if (EPI == 0) {
                    *(float2*)(C + idx) = make_float2(v0, v1);
                } else {
                    float2 g = *(const float2*)(Gbuf + idx);
                    float h0 = silu_f(g.x) * v0;
                    float h1 = silu_f(g.y) * v1;
                    bf16 hh0 = __float2bfloat16(h0);
                    bf16 hh1 = __float2bfloat16(h1);
                    bf16 hl0 = __float2bfloat16(h0 - __bfloat162float(hh0));
                    bf16 hl1 = __float2bfloat16(h1 - __bfloat162float(hh1));
                    *(__nv_bfloat162*)(Hhi + idx) = __nv_bfloat162(hh0, hh1);
                    *(__nv_bfloat162*)(Hlo + idx) = __nv_bfloat162(hl0, hl1);
                }
            }
        }
    }
}

// ---------------- combine ----------------
__global__ void k_combine(float* __restrict__ out, const float* __restrict__ pair, int T) {
    int t = blockIdx.x;
    float w0 = g_tw[2 * t], w1 = g_tw[2 * t + 1];
    size_t p0 = (size_t)g_slot[2 * t] * DIM;
    size_t p1 = (size_t)g_slot[2 * t + 1] * DIM;
    size_t ob = (size_t)t * DIM;
    for (int d = threadIdx.x * 4; d < DIM; d += blockDim.x * 4) {
        float4 a = *(const float4*)(pair + p0 + d);
        float4 b = *(const float4*)(pair + p1 + d);
        float4 o = *(const float4*)(out + ob + d);
        o.x += w0 * a.x + w1 * b.x;
        o.y += w0 * a.y + w1 * b.y;
        o.z += w0 * a.z + w1 * b.z;
        o.w += w0 * a.w + w1 * b.w;
        *(float4*)(out + ob + d) = o;
    }
}

// ---------------- launch ----------------
extern "C" void kernel_launch(void* const* d_in, const int* in_sizes, int n_in,
                              void* d_out, int out_size) {
    const float* x  = (const float*)d_in[0];
    const float* gw = (const float*)d_in[1];
    const float* sg = (const float*)d_in[2];
    const float* su = (const float*)d_in[3];
    const float* sd = (const float*)d_in[4];
    const float* eg = (const float*)d_in[5];
    const float* eu = (const float*)d_in[6];
    const float* ed = (const float*)d_in[7];
    float* out = (float*)d_out;

    int T = in_sizes[0] / DIM;       // 8192
    int A2 = 2 * T;

    float *pG, *pPair;
    int *pOff;
    bf16 *pXhi, *pXlo, *pXGhi, *pXGlo, *pHhi, *pHlo;
    bf16 *pSGhi, *pSGlo, *pSUhi, *pSUlo, *pSDhi, *pSDlo;
    bf16 *pEGhi, *pEGlo, *pEUhi, *pEUlo, *pEDhi, *pEDlo;
    cudaGetSymbolAddress((void**)&pG, g_G);
    cudaGetSymbolAddress((void**)&pPair, g_pair);
    cudaGetSymbolAddress((void**)&pOff, g_off);
    cudaGetSymbolAddress((void**)&pXhi, g_xhi);
    cudaGetSymbolAddress((void**)&pXlo, g_xlo);
    cudaGetSymbolAddress((void**)&pXGhi, g_xghi);
    cudaGetSymbolAddress((void**)&pXGlo, g_xglo);
    cudaGetSymbolAddress((void**)&pHhi, g_Hhi);
    cudaGetSymbolAddress((void**)&pHlo, g_Hlo);
    cudaGetSymbolAddress((void**)&pSGhi, g_sgThi);
    cudaGetSymbolAddress((void**)&pSGlo, g_sgTlo);
    cudaGetSymbolAddress((void**)&pSUhi, g_suThi);
    cudaGetSymbolAddress((void**)&pSUlo, g_suTlo);
    cudaGetSymbolAddress((void**)&pSDhi, g_sdThi);
    cudaGetSymbolAddress((void**)&pSDlo, g_sdTlo);
    cudaGetSymbolAddress((void**)&pEGhi, g_egThi);
    cudaGetSymbolAddress((void**)&pEGlo, g_egTlo);
    cudaGetSymbolAddress((void**)&pEUhi, g_euThi);
    cudaGetSymbolAddress((void**)&pEUlo, g_euTlo);
    cudaGetSymbolAddress((void**)&pEDhi, g_edThi);
    cudaGetSymbolAddress((void**)&pEDlo, g_edTlo);

    cudaFuncSetAttribute(k_gemm_p<0>, cudaFuncAttributeMaxDynamicSharedMemorySize, GEMM_SMEM);
    cudaFuncSetAttribute(k_gemm_p<1>, cudaFuncAttributeMaxDynamicSharedMemorySize, GEMM_SMEM);

    k_init<<<1, 32>>>();
    k_router<<<(T + 7) / 8, 256>>>(x, gw, T);
    k_scan<<<1, 1>>>(out, T, (size_t)out_size > (size_t)T * DIM ? 1 : 0);
    k_scatter<<<(T + 255) / 256, 256>>>(T);

    // splits / transposes / gather
    k_split<<<(T * DIM / 4 + 255) / 256, 256>>>((const float4*)x, (__nv_bfloat162*)pXhi,
                                                (__nv_bfloat162*)pXlo, T * DIM / 4);
    k_gsplit<<<A2, 256>>>(x, (__nv_bfloat162*)pXGhi, (__nv_bfloat162*)pXGlo);
    k_tsplit<<<dim3(IDIM / 32, DIM / 32, 1), 256>>>(sg, pSGhi, pSGlo, DIM, IDIM);
    k_tsplit<<<dim3(IDIM / 32, DIM / 32, 1), 256>>>(su, pSUhi, pSUlo, DIM, IDIM);
    k_tsplit<<<dim3(DIM / 32, IDIM / 32, 1), 256>>>(sd, pSDhi, pSDlo, IDIM, DIM);
    k_tsplit<<<dim3(IDIM / 32, DIM / 32, NE), 256>>>(eg, pEGhi, pEGlo, DIM, IDIM);
    k_tsplit<<<dim3(IDIM / 32, DIM / 32, NE), 256>>>(eu, pEUhi, pEUlo, DIM, IDIM);
    k_tsplit<<<dim3(DIM / 32, IDIM / 32, NE), 256>>>(ed, pEDhi, pEDlo, IDIM, DIM);

    // shared expert
    k_gemm_p<0><<<dim3(IDIM / 128, T / 128, 1), 256, GEMM_SMEM>>>(
        pXhi, pXlo, pSGhi, pSGlo, pG, nullptr, nullptr, nullptr,
        nullptr, T, IDIM, DIM, 0, DIM / BK);
    k_gemm_p<1><<<dim3(IDIM / 128, T / 128, 1), 256, GEMM_SMEM>>>(
        pXhi, pXlo, pSUhi, pSUlo, nullptr, pG, pHhi, pHlo,
        nullptr, T, IDIM, DIM, 0, DIM / BK);
    k_gemm_p<0><<<dim3(DIM / 128, T / 128, 1), 256, GEMM_SMEM>>>(
        pHhi, pHlo, pSDhi, pSDlo, out, nullptr, nullptr, nullptr,
        nullptr, T, DIM, IDIM, 0, IDIM / BK);

    // routed experts
    int mt = (A2 + 127) / 128;
    k_gemm_p<0><<<dim3(IDIM / 128, mt, NE), 256, GEMM_SMEM>>>(
        pXGhi, pXGlo, pEGhi, pEGlo, pG, nullptr, nullptr, nullptr,
        pOff, A2, IDIM, DIM, (long)DIM * IDIM, DIM / BK);
    k_gemm_p<1><<<dim3(IDIM / 128, mt, NE), 256, GEMM_SMEM>>>(
        pXGhi, pXGlo, pEUhi, pEUlo, nullptr, pG, pHhi, pHlo,
        pOff, A2, IDIM, DIM, (long)DIM * IDIM, DIM / BK);
    k_gemm_p<0><<<dim3(DIM / 128, mt, NE), 256, GEMM_SMEM>>>(
        pHhi, pHlo, pEDhi, pEDlo, pPair, nullptr, nullptr, nullptr,
        pOff, A2, DIM, IDIM, (long)IDIM * DIM, IDIM / BK);

    k_combine<<<T, 256>>>(out, pPair, T);
}

// round 8
// speedup vs baseline: 2.4318x; 1.3019x over previous
#include <cuda_runtime.h>
#include <cuda_bf16.h>
#include <cstdint>
#include <math.h>

#define NE 8
#define DIM 1024
#define IDIM 2048
#define TKN_MAX 8192
#define ASG_MAX 16384

typedef __nv_bfloat16 bf16;

// ---------------- device scratch (no allocs allowed) ----------------
__device__ float g_G[(size_t)ASG_MAX * IDIM];      // fp32 gate-proj intermediate
__device__ float g_pair[(size_t)ASG_MAX * DIM];    // per-assignment routed output
__device__ bf16  g_Hhi[(size_t)ASG_MAX * IDIM];    // swiglu output hi/lo
__device__ bf16  g_Hlo[(size_t)ASG_MAX * IDIM];
__device__ bf16  g_xhi[(size_t)TKN_MAX * DIM];     // x split (shared expert)
__device__ bf16  g_xlo[(size_t)TKN_MAX * DIM];
__device__ bf16  g_xghi[(size_t)ASG_MAX * DIM];    // gathered x split (routed)
__device__ bf16  g_xglo[(size_t)ASG_MAX * DIM];
// transposed weights [N, K] hi/lo
__device__ bf16  g_sgThi[(size_t)IDIM * DIM], g_sgTlo[(size_t)IDIM * DIM];
__device__ bf16  g_suThi[(size_t)IDIM * DIM], g_suTlo[(size_t)IDIM * DIM];
__device__ bf16  g_sdThi[(size_t)DIM * IDIM], g_sdTlo[(size_t)DIM * IDIM];
__device__ bf16  g_egThi[(size_t)NE * IDIM * DIM], g_egTlo[(size_t)NE * IDIM * DIM];
__device__ bf16  g_euThi[(size_t)NE * IDIM * DIM], g_euTlo[(size_t)NE * IDIM * DIM];
__device__ bf16  g_edThi[(size_t)NE * DIM * IDIM], g_edTlo[(size_t)NE * DIM * IDIM];
__device__ int   g_assign[ASG_MAX];
__device__ int   g_te[ASG_MAX];
__device__ float g_tw[ASG_MAX];
__device__ int   g_slot[ASG_MAX];
__device__ int   g_counts[NE];
__device__ int   g_off[NE + 1];
__device__ int   g_cursor[NE];
__device__ float g_psum[NE];

// ---------------- mma / ldmatrix / cp.async helpers ----------------
__device__ __forceinline__ void mma_bf16(float* d, const unsigned* a, const unsigned* b) {
    asm volatile("mma.sync.aligned.m16n8k16.row.col.f32.bf16.bf16.f32 "
                 "{%0,%1,%2,%3}, {%4,%5,%6,%7}, {%8,%9}, {%0,%1,%2,%3};"
                 : "+f"(d[0]), "+f"(d[1]), "+f"(d[2]), "+f"(d[3])
                 : "r"(a[0]), "r"(a[1]), "r"(a[2]), "r"(a[3]), "r"(b[0]), "r"(b[1]));
}
__device__ __forceinline__ void ldsm4(unsigned* r, unsigned addr) {
    asm volatile("ldmatrix.sync.aligned.m8n8.x4.shared.b16 {%0,%1,%2,%3}, [%4];"
                 : "=r"(r[0]), "=r"(r[1]), "=r"(r[2]), "=r"(r[3]) : "r"(addr));
}
#define CPA16(dst, src) \
    asm volatile("cp.async.cg.shared.global [%0], [%1], 16;" :: "r"(dst), "l"(src))
#define CP_COMMIT() asm volatile("cp.async.commit_group;" ::: "memory")
#define CP_WAIT1()  asm volatile("cp.async.wait_group 1;" ::: "memory")

__device__ __forceinline__ float silu_f(float x) { return x / (1.f + expf(-x)); }

// ---------------- init ----------------
__global__ void k_init() {
    int i = threadIdx.x;
    if (i < NE) { g_counts[i] = 0; g_psum[i] = 0.f; }
}

// ---------------- split: fp32 -> bf16 hi + bf16 lo ----------------
__global__ void k_split(const float4* __restrict__ in, __nv_bfloat162* __restrict__ hi,
                        __nv_bfloat162* __restrict__ lo, int n4) {
    int i = blockIdx.x * blockDim.x + threadIdx.x;
    if (i < n4) {
        float4 v = in[i];
        bf16 h0 = __float2bfloat16(v.x), h1 = __float2bfloat16(v.y);
        bf16 h2 = __float2bfloat16(v.z), h3 = __float2bfloat16(v.w);
        bf16 l0 = __float2bfloat16(v.x - __bfloat162float(h0));
        bf16 l1 = __float2bfloat16(v.y - __bfloat162float(h1));
        bf16 l2 = __float2bfloat16(v.z - __bfloat162float(h2));
        bf16 l3 = __float2bfloat16(v.w - __bfloat162float(h3));
        hi[2 * i]     = __nv_bfloat162(h0, h1);
        hi[2 * i + 1] = __nv_bfloat162(h2, h3);
        lo[2 * i]     = __nv_bfloat162(l0, l1);
        lo[2 * i + 1] = __nv_bfloat162(l2, l3);
    }
}

// ---------------- transpose + split: W[K,N] fp32 -> Wt[N,K] bf16 hi/lo ----------------
__global__ void k_tsplit(const float* __restrict__ W, bf16* __restrict__ hi,
                         bf16* __restrict__ lo, int K, int N) {
    __shared__ float t[32][33];
    size_t eo = (size_t)blockIdx.z * K * N;
    int k0 = blockIdx.y * 32, n0 = blockIdx.x * 32;
    int tx = threadIdx.x & 31, ty = threadIdx.x >> 5;
#pragma unroll
    for (int r = ty; r < 32; r += 8)
        t[r][tx] = W[eo + (size_t)(k0 + r) * N + n0 + tx];
    __syncthreads();
#pragma unroll
    for (int r = ty; r < 32; r += 8) {
        float v = t[tx][r];
        bf16 h = __float2bfloat16(v);
        bf16 l = __float2bfloat16(v - __bfloat162float(h));
        size_t o = eo + (size_t)(n0 + r) * K + k0 + tx;
        hi[o] = h; lo[o] = l;
    }
}

// ---------------- gather + split ----------------
__global__ void k_gsplit(const float* __restrict__ x, __nv_bfloat162* __restrict__ hi,
                         __nv_bfloat162* __restrict__ lo) {
    int a = blockIdx.x;
    int t = g_assign[a];
    const float4* src = (const float4*)(x + (size_t)t * DIM);
    int i = threadIdx.x;                 // 256 threads, DIM/4 = 256
    float4 v = src[i];
    bf16 h0 = __float2bfloat16(v.x), h1 = __float2bfloat16(v.y);
    bf16 h2 = __float2bfloat16(v.z), h3 = __float2bfloat16(v.w);
    bf16 l0 = __float2bfloat16(v.x - __bfloat162float(h0));
    bf16 l1 = __float2bfloat16(v.y - __bfloat162float(h1));
    bf16 l2 = __float2bfloat16(v.z - __bfloat162float(h2));
    bf16 l3 = __float2bfloat16(v.w - __bfloat162float(h3));
    size_t o = (size_t)a * (DIM / 2) + 2 * i;
    hi[o]     = __nv_bfloat162(h0, h1);
    hi[o + 1] = __nv_bfloat162(h2, h3);
    lo[o]     = __nv_bfloat162(l0, l1);
    lo[o + 1] = __nv_bfloat162(l2, l3);
}

// ---------------- router ----------------
__global__ void k_router(const float* __restrict__ x, const float* __restrict__ gw, int T) {
    __shared__ float sP[NE];
    if (threadIdx.x < NE) sP[threadIdx.x] = 0.f;
    __syncthreads();

    int warp = (blockIdx.x * blockDim.x + threadIdx.x) >> 5;
    int lane = threadIdx.x & 31;
    if (warp < T) {
        const float* xr = x + (size_t)warp * DIM;
        float acc[NE];
#pragma unroll
        for (int e = 0; e < NE; e++) acc[e] = 0.f;
        for (int i = lane; i < DIM; i += 32) {
            float xv = xr[i];
#pragma unroll
            for (int e = 0; e < NE; e++) acc[e] = fmaf(xv, gw[e * DIM + i], acc[e]);
        }
#pragma unroll
        for (int e = 0; e < NE; e++) {
#pragma unroll
            for (int o = 16; o; o >>= 1) acc[e] += __shfl_xor_sync(0xffffffffu, acc[e], o);
        }
        if (lane == 0) {
            float mx = acc[0];
#pragma unroll
            for (int e = 1; e < NE; e++) mx = fmaxf(mx, acc[e]);
            float ex[NE]; float s = 0.f;
#pragma unroll
            for (int e = 0; e < NE; e++) { ex[e] = expf(acc[e] - mx); s += ex[e]; }
            float inv = 1.f / s;
#pragma unroll
            for (int e = 0; e < NE; e++) atomicAdd(&sP[e], ex[e] * inv);
            int i0 = 0;
#pragma unroll
            for (int e = 1; e < NE; e++) if (acc[e] > acc[i0]) i0 = e;
            int i1 = (i0 == 0) ? 1 : 0;
#pragma unroll
            for (int e = 0; e < NE; e++) if (e != i0 && acc[e] > acc[i1]) i1 = e;
            float m2 = fmaxf(acc[i0], acc[i1]);
            float e0 = expf(acc[i0] - m2), e1 = expf(acc[i1] - m2);
            float wsum = e0 + e1;
            g_te[2 * warp] = i0; g_te[2 * warp + 1] = i1;
            g_tw[2 * warp] = e0 / wsum; g_tw[2 * warp + 1] = e1 / wsum;
            atomicAdd(&g_counts[i0], 1);
            atomicAdd(&g_counts[i1], 1);
        }
    }
    __syncthreads();
    if (threadIdx.x < NE) atomicAdd(&g_psum[threadIdx.x], sP[threadIdx.x]);
}

// ---------------- scan ----------------
__global__ void k_scan(float* __restrict__ out, int T, int write_aux) {
    if (threadIdx.x == 0 && blockIdx.x == 0) {
        int o = 0;
        float aux = 0.f;
        for (int e = 0; e < NE; e++) {
            g_off[e] = o; g_cursor[e] = o;
            float f = (float)g_counts[e] / (float)(T * 2);
            float P = g_psum[e] / (float)T;
            aux += f * P;
            o += g_counts[e];
        }
        g_off[NE] = o;
        if (write_aux) out[(size_t)T * DIM] = (float)NE * aux;
    }
}

// ---------------- scatter ----------------
__global__ void k_scatter(int T) {
    int t = blockIdx.x * blockDim.x + threadIdx.x;
    if (t < T) {
#pragma unroll
        for (int k = 0; k < 2; k++) {
            int e = g_te[2 * t + k];
            int pos = atomicAdd(&g_cursor[e], 1);
            g_assign[pos] = t;
            g_slot[2 * t + k] = pos;
        }
    }
}

// ---------------- pipelined bf16x3 HMMA GEMM, full-line loads ----------------
// C[128,128] tile: C[m,n] = sum_k A[m,k]*Bt[n,k]; A,Bt bf16 hi/lo, K-major.
// BK=64 (row = one 128B line), SW128 swizzle, 3-stage cp.async ring.
// EPI==0: fp32 C.  EPI==1: h = silu(Gbuf)*acc -> bf16 hi/lo (Hhi/Hlo).
#define BK 64
#define STG 3
#define TILE_B 16384                   // 128 rows x 128B
#define STAGE_B (4 * TILE_B)           // Ahi, Alo, Bhi, Blo
#define GEMM_SMEM (STG * STAGE_B)      // 196608 bytes

template <int EPI>
__global__ __launch_bounds__(256) void k_gemm_p(
    const bf16* __restrict__ Ahi, const bf16* __restrict__ Alo,
    const bf16* __restrict__ BhiT, const bf16* __restrict__ BloT,
    float* __restrict__ C, const float* __restrict__ Gbuf,
    bf16* __restrict__ Hhi, bf16* __restrict__ Hlo,
    const int* __restrict__ seg_off,
    int M, int N, int K, long strideB, int NST)
{
    int m_lo = 0, m_hi = M;
    const bf16* Bh = BhiT;
    const bf16* Bl = BloT;
    if (seg_off) {
        int s = blockIdx.z;
        m_lo = seg_off[s]; m_hi = seg_off[s + 1];
        Bh += (size_t)s * strideB;
        Bl += (size_t)s * strideB;
    }
    int m0 = m_lo + blockIdx.y * 128;
    if (m0 >= m_hi) return;
    int n0 = blockIdx.x * 128;

    extern __shared__ __align__(1024) char sm[];
    int tid = threadIdx.x, lane = tid & 31, wid = tid >> 5;
    int wm = wid >> 2, wn = wid & 3;

    unsigned sbase;
    asm("{ .reg .u64 t; cvta.to.shared.u64 t, %1; cvt.u32.u64 %0, t; }"
        : "=r"(sbase) : "l"(sm));

    // ---- load addressing: thread covers chunk (tid&7) of rows (tid>>3)+32j ----
    int chunk = tid & 7;
    int r0 = tid >> 3;                 // 0..31
    size_t rowA[4], rowB[4];
#pragma unroll
    for (int j = 0; j < 4; j++) {
        int r = r0 + 32 * j;
        int gr = m0 + r; if (gr > M - 1) gr = M - 1;
        rowA[j] = (size_t)gr * K * 2 + (size_t)chunk * 16;
        rowB[j] = (size_t)(n0 + r) * K * 2 + (size_t)chunk * 16;
    }
    unsigned dst0 = (unsigned)(r0 * 128 + ((chunk * 16) ^ ((r0 & 7) << 4)));

    auto load_stage = [&](int stage, int buf) {
        unsigned d = sbase + (unsigned)buf * STAGE_B + dst0;
        size_t ko = (size_t)stage * BK * 2;
#pragma unroll
        for (int j = 0; j < 4; j++) {
            unsigned dj = d + (unsigned)j * 4096;
            CPA16(dj,              (const char*)Ahi + rowA[j] + ko);
            CPA16(dj + TILE_B,     (const char*)Alo + rowA[j] + ko);
            CPA16(dj + 2 * TILE_B, (const char*)Bh  + rowB[j] + ko);
            CPA16(dj + 3 * TILE_B, (const char*)Bl  + rowB[j] + ko);
        }
    };

    // ---- accumulators ----
    float acc[4][4][4];
#pragma unroll
    for (int i = 0; i < 4; i++)
#pragma unroll
        for (int j = 0; j < 4; j++)
#pragma unroll
            for (int r = 0; r < 4; r++) acc[i][j][r] = 0.f;

    // ---- ldmatrix per-lane constants ----
    unsigned laneRow = (unsigned)((lane & 15) * 128);
    unsigned chunkb = (unsigned)((lane >> 4) << 4);
    unsigned swx = (unsigned)((lane & 7) << 4);

    // ---- prologue ----
    if (0 < NST) load_stage(0, 0);
    CP_COMMIT();
    if (1 < NST) load_stage(1, 1);
    CP_COMMIT();

    for (int i = 0; i < NST; i++) {
        CP_WAIT1();
        __syncthreads();
        if (i + 2 < NST) load_stage(i + 2, (i + 2) % STG);
        CP_COMMIT();

        unsigned tb = sbase + (unsigned)(i % STG) * STAGE_B;

#pragma unroll
        for (int ks = 0; ks < 4; ks++) {
            unsigned xoff = (((unsigned)(ks * 32)) | chunkb) ^ swx;
            unsigned bh[4][2], bl[4][2];
#pragma unroll
            for (int nb = 0; nb < 2; nb++) {
                unsigned ro = (unsigned)((wn * 32 + nb * 16) * 128) + laneRow + xoff;
                unsigned t[4];
                ldsm4(t, tb + 2 * TILE_B + ro);
                bh[2 * nb][0] = t[0]; bh[2 * nb][1] = t[2];
                bh[2 * nb + 1][0] = t[1]; bh[2 * nb + 1][1] = t[3];
                ldsm4(t, tb + 3 * TILE_B + ro);
                bl[2 * nb][0] = t[0]; bl[2 * nb][1] = t[2];
                bl[2 * nb + 1][0] = t[1]; bl[2 * nb + 1][1] = t[3];
            }
            unsigned ah[4][4], al[4][4];
#pragma unroll
            for (int mi = 0; mi < 4; mi++) {
                unsigned ro = (unsigned)((wm * 64 + mi * 16) * 128) + laneRow + xoff;
                ldsm4(ah[mi], tb + ro);
                ldsm4(al[mi], tb + TILE_B + ro);
            }
            // term-major: accumulator reuse distance = 16 MMAs
#pragma unroll
            for (int mi = 0; mi < 4; mi++)
#pragma unroll
                for (int ni = 0; ni < 4; ni++) mma_bf16(acc[mi][ni], ah[mi], bh[ni]);
#pragma unroll
            for (int mi = 0; mi < 4; mi++)
#pragma unroll
                for (int ni = 0; ni < 4; ni++) mma_bf16(acc[mi][ni], al[mi], bh[ni]);
#pragma unroll
            for (int mi = 0; mi < 4; mi++)
#pragma unroll
                for (int ni = 0; ni < 4; ni++) mma_bf16(acc[mi][ni], ah[mi], bl[ni]);
        }
        __syncthreads();
    }

    // ---- epilogue ----
    int mrow = m0 + wm * 64 + (lane >> 2);
    int mcol = n0 + wn * 32 + ((lane & 3) << 1);
#pragma unroll
    for (int mi = 0; mi < 4; mi++) {
#pragma unroll
        for (int half = 0; half < 2; half++) {
            int r = mrow + mi * 16 + half * 8;
            if (r >= m_hi) continue;
#pragma unroll
            for (int ni = 0; ni < 4; ni++) {
                int c = mcol + ni * 8;
                size_t idx = (size_t)r * N + c;
                float v0 = acc[mi][ni][2 * half];
                float v1 = acc[mi][ni][2 * half + 1];
                if (EPI == 0) {
                    *(float2*)(C + idx) = make_float2(v0, v1);
                } else {
                    float2 g = *(const float2*)(Gbuf + idx);
                    float h0 = silu_f(g.x) * v0;
                    float h1 = silu_f(g.y) * v1;
                    bf16 hh0 = __float2bfloat16(h0);
                    bf16 hh1 = __float2bfloat16(h1);
                    bf16 hl0 = __float2bfloat16(h0 - __bfloat162float(hh0));
                    bf16 hl1 = __float2bfloat16(h1 - __bfloat162float(hh1));
                    *(__nv_bfloat162*)(Hhi + idx) = __nv_bfloat162(hh0, hh1);
                    *(__nv_bfloat162*)(Hlo + idx) = __nv_bfloat162(hl0, hl1);
                }
            }
        }
    }
}

// ---------------- combine ----------------
__global__ void k_combine(float* __restrict__ out, const float* __restrict__ pair, int T) {
    int t = blockIdx.x;
    float w0 = g_tw[2 * t], w1 = g_tw[2 * t + 1];
    size_t p0 = (size_t)g_slot[2 * t] * DIM;
    size_t p1 = (size_t)g_slot[2 * t + 1] * DIM;
    size_t ob = (size_t)t * DIM;
    for (int d = threadIdx.x * 4; d < DIM; d += blockDim.x * 4) {
        float4 a = *(const float4*)(pair + p0 + d);
        float4 b = *(const float4*)(pair + p1 + d);
        float4 o = *(const float4*)(out + ob + d);
        o.x += w0 * a.x + w1 * b.x;
        o.y += w0 * a.y + w1 * b.y;
        o.z += w0 * a.z + w1 * b.z;
        o.w += w0 * a.w + w1 * b.w;
        *(float4*)(out + ob + d) = o;
    }
}

// ---------------- launch ----------------
extern "C" void kernel_launch(void* const* d_in, const int* in_sizes, int n_in,
                              void* d_out, int out_size) {
    const float* x  = (const float*)d_in[0];
    const float* gw = (const float*)d_in[1];
    const float* sg = (const float*)d_in[2];
    const float* su = (const float*)d_in[3];
    const float* sd = (const float*)d_in[4];
    const float* eg = (const float*)d_in[5];
    const float* eu = (const float*)d_in[6];
    const float* ed = (const float*)d_in[7];
    float* out = (float*)d_out;

    int T = in_sizes[0] / DIM;       // 8192
    int A2 = 2 * T;

    float *pG, *pPair;
    int *pOff;
    bf16 *pXhi, *pXlo, *pXGhi, *pXGlo, *pHhi, *pHlo;
    bf16 *pSGhi, *pSGlo, *pSUhi, *pSUlo, *pSDhi, *pSDlo;
    bf16 *pEGhi, *pEGlo, *pEUhi, *pEUlo, *pEDhi, *pEDlo;
    cudaGetSymbolAddress((void**)&pG, g_G);
    cudaGetSymbolAddress((void**)&pPair, g_pair);
    cudaGetSymbolAddress((void**)&pOff, g_off);
    cudaGetSymbolAddress((void**)&pXhi, g_xhi);
    cudaGetSymbolAddress((void**)&pXlo, g_xlo);
    cudaGetSymbolAddress((void**)&pXGhi, g_xghi);
    cudaGetSymbolAddress((void**)&pXGlo, g_xglo);
    cudaGetSymbolAddress((void**)&pHhi, g_Hhi);
    cudaGetSymbolAddress((void**)&pHlo, g_Hlo);
    cudaGetSymbolAddress((void**)&pSGhi, g_sgThi);
    cudaGetSymbolAddress((void**)&pSGlo, g_sgTlo);
    cudaGetSymbolAddress((void**)&pSUhi, g_suThi);
    cudaGetSymbolAddress((void**)&pSUlo, g_suTlo);
    cudaGetSymbolAddress((void**)&pSDhi, g_sdThi);
    cudaGetSymbolAddress((void**)&pSDlo, g_sdTlo);
    cudaGetSymbolAddress((void**)&pEGhi, g_egThi);
    cudaGetSymbolAddress((void**)&pEGlo, g_egTlo);
    cudaGetSymbolAddress((void**)&pEUhi, g_euThi);
    cudaGetSymbolAddress((void**)&pEUlo, g_euTlo);
    cudaGetSymbolAddress((void**)&pEDhi, g_edThi);
    cudaGetSymbolAddress((void**)&pEDlo, g_edTlo);

    cudaFuncSetAttribute(k_gemm_p<0>, cudaFuncAttributeMaxDynamicSharedMemorySize, GEMM_SMEM);
    cudaFuncSetAttribute(k_gemm_p<1>, cudaFuncAttributeMaxDynamicSharedMemorySize, GEMM_SMEM);

    k_init<<<1, 32>>>();
    k_router<<<(T + 7) / 8, 256>>>(x, gw, T);
    k_scan<<<1, 1>>>(out, T, (size_t)out_size > (size_t)T * DIM ? 1 : 0);
    k_scatter<<<(T + 255) / 256, 256>>>(T);

    // splits / transposes / gather
    k_split<<<(T * DIM / 4 + 255) / 256, 256>>>((const float4*)x, (__nv_bfloat162*)pXhi,
                                                (__nv_bfloat162*)pXlo, T * DIM / 4);
    k_gsplit<<<A2, 256>>>(x, (__nv_bfloat162*)pXGhi, (__nv_bfloat162*)pXGlo);
    k_tsplit<<<dim3(IDIM / 32, DIM / 32, 1), 256>>>(sg, pSGhi, pSGlo, DIM, IDIM);
    k_tsplit<<<dim3(IDIM / 32, DIM / 32, 1), 256>>>(su, pSUhi, pSUlo, DIM, IDIM);
    k_tsplit<<<dim3(DIM / 32, IDIM / 32, 1), 256>>>(sd, pSDhi, pSDlo, IDIM, DIM);
    k_tsplit<<<dim3(IDIM / 32, DIM / 32, NE), 256>>>(eg, pEGhi, pEGlo, DIM, IDIM);
    k_tsplit<<<dim3(IDIM / 32, DIM / 32, NE), 256>>>(eu, pEUhi, pEUlo, DIM, IDIM);
    k_tsplit<<<dim3(DIM / 32, IDIM / 32, NE), 256>>>(ed, pEDhi, pEDlo, IDIM, DIM);

    // shared expert
    k_gemm_p<0><<<dim3(IDIM / 128, T / 128, 1), 256, GEMM_SMEM>>>(
        pXhi, pXlo, pSGhi, pSGlo, pG, nullptr, nullptr, nullptr,
        nullptr, T, IDIM, DIM, 0, DIM / BK);
    k_gemm_p<1><<<dim3(IDIM / 128, T / 128, 1), 256, GEMM_SMEM>>>(
        pXhi, pXlo, pSUhi, pSUlo, nullptr, pG, pHhi, pHlo,
        nullptr, T, IDIM, DIM, 0, DIM / BK);
    k_gemm_p<0><<<dim3(DIM / 128, T / 128, 1), 256, GEMM_SMEM>>>(
        pHhi, pHlo, pSDhi, pSDlo, out, nullptr, nullptr, nullptr,
        nullptr, T, DIM, IDIM, 0, IDIM / BK);

    // routed experts
    int mt = (A2 + 127) / 128;
    k_gemm_p<0><<<dim3(IDIM / 128, mt, NE), 256, GEMM_SMEM>>>(
        pXGhi, pXGlo, pEGhi, pEGlo, pG, nullptr, nullptr, nullptr,
        pOff, A2, IDIM, DIM, (long)DIM * IDIM, DIM / BK);
    k_gemm_p<1><<<dim3(IDIM / 128, mt, NE), 256, GEMM_SMEM>>>(
        pXGhi, pXGlo, pEUhi, pEUlo, nullptr, pG, pHhi, pHlo,
        pOff, A2, IDIM, DIM, (long)DIM * IDIM, DIM / BK);
    k_gemm_p<0><<<dim3(DIM / 128, mt, NE), 256, GEMM_SMEM>>>(
        pHhi, pHlo, pEDhi, pEDlo, pPair, nullptr, nullptr, nullptr,
        pOff, A2, DIM, IDIM, (long)IDIM * DIM, IDIM / BK);

    k_combine<<<T, 256>>>(out, pPair, T);
}

// round 9
// speedup vs baseline: 2.4409x; 1.0038x over previous
#include <cuda_runtime.h>
#include <cuda_bf16.h>
#include <cstdint>
#include <math.h>

#define NE 8
#define DIM 1024
#define IDIM 2048
#define TKN_MAX 8192
#define ASG_MAX 16384

typedef __nv_bfloat16 bf16;

// ---------------- device scratch (no allocs allowed) ----------------
__device__ float g_G[(size_t)ASG_MAX * IDIM];
__device__ float g_pair[(size_t)ASG_MAX * DIM];
__device__ bf16  g_Hhi[(size_t)ASG_MAX * IDIM];
__device__ bf16  g_Hlo[(size_t)ASG_MAX * IDIM];
__device__ bf16  g_xhi[(size_t)TKN_MAX * DIM];
__device__ bf16  g_xlo[(size_t)TKN_MAX * DIM];
__device__ bf16  g_xghi[(size_t)ASG_MAX * DIM];
__device__ bf16  g_xglo[(size_t)ASG_MAX * DIM];
__device__ bf16  g_sgThi[(size_t)IDIM * DIM], g_sgTlo[(size_t)IDIM * DIM];
__device__ bf16  g_suThi[(size_t)IDIM * DIM], g_suTlo[(size_t)IDIM * DIM];
__device__ bf16  g_sdThi[(size_t)DIM * IDIM], g_sdTlo[(size_t)DIM * IDIM];
__device__ bf16  g_egThi[(size_t)NE * IDIM * DIM], g_egTlo[(size_t)NE * IDIM * DIM];
__device__ bf16  g_euThi[(size_t)NE * IDIM * DIM], g_euTlo[(size_t)NE * IDIM * DIM];
__device__ bf16  g_edThi[(size_t)NE * DIM * IDIM], g_edTlo[(size_t)NE * DIM * IDIM];
__device__ int   g_assign[ASG_MAX];
__device__ int   g_te[ASG_MAX];
__device__ float g_tw[ASG_MAX];
__device__ int   g_slot[ASG_MAX];
__device__ int   g_counts[NE];
__device__ int   g_off[NE + 1];
__device__ int   g_cursor[NE];
__device__ float g_psum[NE];

// ---------------- mma / ldmatrix / cp.async helpers ----------------
__device__ __forceinline__ void mma_bf16(float* d, const unsigned* a, const unsigned* b) {
    asm volatile("mma.sync.aligned.m16n8k16.row.col.f32.bf16.bf16.f32 "
                 "{%0,%1,%2,%3}, {%4,%5,%6,%7}, {%8,%9}, {%0,%1,%2,%3};"
                 : "+f"(d[0]), "+f"(d[1]), "+f"(d[2]), "+f"(d[3])
                 : "r"(a[0]), "r"(a[1]), "r"(a[2]), "r"(a[3]), "r"(b[0]), "r"(b[1]));
}
__device__ __forceinline__ void ldsm4(unsigned* r, unsigned addr) {
    asm volatile("ldmatrix.sync.aligned.m8n8.x4.shared.b16 {%0,%1,%2,%3}, [%4];"
                 : "=r"(r[0]), "=r"(r[1]), "=r"(r[2]), "=r"(r[3]) : "r"(addr));
}
#define CPA16(dst, src) \
    asm volatile("cp.async.cg.shared.global [%0], [%1], 16;" :: "r"(dst), "l"(src))
#define CP_COMMIT() asm volatile("cp.async.commit_group;" ::: "memory")
#define CP_WAIT1()  asm volatile("cp.async.wait_group 1;" ::: "memory")

__device__ __forceinline__ float silu_f(float x) { return x / (1.f + expf(-x)); }

// ---------------- init ----------------
__global__ void k_init() {
    int i = threadIdx.x;
    if (i < NE) { g_counts[i] = 0; g_psum[i] = 0.f; }
}

// ---------------- split ----------------
__global__ void k_split(const float4* __restrict__ in, __nv_bfloat162* __restrict__ hi,
                        __nv_bfloat162* __restrict__ lo, int n4) {
    int i = blockIdx.x * blockDim.x + threadIdx.x;
    if (i < n4) {
        float4 v = in[i];
        bf16 h0 = __float2bfloat16(v.x), h1 = __float2bfloat16(v.y);
        bf16 h2 = __float2bfloat16(v.z), h3 = __float2bfloat16(v.w);
        bf16 l0 = __float2bfloat16(v.x - __bfloat162float(h0));
        bf16 l1 = __float2bfloat16(v.y - __bfloat162float(h1));
        bf16 l2 = __float2bfloat16(v.z - __bfloat162float(h2));
        bf16 l3 = __float2bfloat16(v.w - __bfloat162float(h3));
        hi[2 * i]     = __nv_bfloat162(h0, h1);
        hi[2 * i + 1] = __nv_bfloat162(h2, h3);
        lo[2 * i]     = __nv_bfloat162(l0, l1);
        lo[2 * i + 1] = __nv_bfloat162(l2, l3);
    }
}

// ---------------- transpose + split ----------------
__global__ void k_tsplit(const float* __restrict__ W, bf16* __restrict__ hi,
                         bf16* __restrict__ lo, int K, int N) {
    __shared__ float t[32][33];
    size_t eo = (size_t)blockIdx.z * K * N;
    int k0 = blockIdx.y * 32, n0 = blockIdx.x * 32;
    int tx = threadIdx.x & 31, ty = threadIdx.x >> 5;
#pragma unroll
    for (int r = ty; r < 32; r += 8)
        t[r][tx] = W[eo + (size_t)(k0 + r) * N + n0 + tx];
    __syncthreads();
#pragma unroll
    for (int r = ty; r < 32; r += 8) {
        float v = t[tx][r];
        bf16 h = __float2bfloat16(v);
        bf16 l = __float2bfloat16(v - __bfloat162float(h));
        size_t o = eo + (size_t)(n0 + r) * K + k0 + tx;
        hi[o] = h; lo[o] = l;
    }
}

// ---------------- gather + split ----------------
__global__ void k_gsplit(const float* __restrict__ x, __nv_bfloat162* __restrict__ hi,
                         __nv_bfloat162* __restrict__ lo) {
    int a = blockIdx.x;
    int t = g_assign[a];
    const float4* src = (const float4*)(x + (size_t)t * DIM);
    int i = threadIdx.x;
    float4 v = src[i];
    bf16 h0 = __float2bfloat16(v.x), h1 = __float2bfloat16(v.y);
    bf16 h2 = __float2bfloat16(v.z), h3 = __float2bfloat16(v.w);
    bf16 l0 = __float2bfloat16(v.x - __bfloat162float(h0));
    bf16 l1 = __float2bfloat16(v.y - __bfloat162float(h1));
    bf16 l2 = __float2bfloat16(v.z - __bfloat162float(h2));
    bf16 l3 = __float2bfloat16(v.w - __bfloat162float(h3));
    size_t o = (size_t)a * (DIM / 2) + 2 * i;
    hi[o]     = __nv_bfloat162(h0, h1);
    hi[o + 1] = __nv_bfloat162(h2, h3);
    lo[o]     = __nv_bfloat162(l0, l1);
    lo[o + 1] = __nv_bfloat162(l2, l3);
}

// ---------------- router ----------------
__global__ void k_router(const float* __restrict__ x, const float* __restrict__ gw, int T) {
    __shared__ float sP[NE];
    if (threadIdx.x < NE) sP[threadIdx.x] = 0.f;
    __syncthreads();

    int warp = (blockIdx.x * blockDim.x + threadIdx.x) >> 5;
    int lane = threadIdx.x & 31;
    if (warp < T) {
        const float* xr = x + (size_t)warp * DIM;
        float acc[NE];
#pragma unroll
        for (int e = 0; e < NE; e++) acc[e] = 0.f;
        for (int i = lane; i < DIM; i += 32) {
            float xv = xr[i];
#pragma unroll
            for (int e = 0; e < NE; e++) acc[e] = fmaf(xv, gw[e * DIM + i], acc[e]);
        }
#pragma unroll
        for (int e = 0; e < NE; e++) {
#pragma unroll
            for (int o = 16; o; o >>= 1) acc[e] += __shfl_xor_sync(0xffffffffu, acc[e], o);
        }
        if (lane == 0) {
            float mx = acc[0];
#pragma unroll
            for (int e = 1; e < NE; e++) mx = fmaxf(mx, acc[e]);
            float ex[NE]; float s = 0.f;
#pragma unroll
            for (int e = 0; e < NE; e++) { ex[e] = expf(acc[e] - mx); s += ex[e]; }
            float inv = 1.f / s;
#pragma unroll
            for (int e = 0; e < NE; e++) atomicAdd(&sP[e], ex[e] * inv);
            int i0 = 0;
#pragma unroll
            for (int e = 1; e < NE; e++) if (acc[e] > acc[i0]) i0 = e;
            int i1 = (i0 == 0) ? 1 : 0;
#pragma unroll
            for (int e = 0; e < NE; e++) if (e != i0 && acc[e] > acc[i1]) i1 = e;
            float m2 = fmaxf(acc[i0], acc[i1]);
            float e0 = expf(acc[i0] - m2), e1 = expf(acc[i1] - m2);
            float wsum = e0 + e1;
            g_te[2 * warp] = i0; g_te[2 * warp + 1] = i1;
            g_tw[2 * warp] = e0 / wsum; g_tw[2 * warp + 1] = e1 / wsum;
            atomicAdd(&g_counts[i0], 1);
            atomicAdd(&g_counts[i1], 1);
        }
    }
    __syncthreads();
    if (threadIdx.x < NE) atomicAdd(&g_psum[threadIdx.x], sP[threadIdx.x]);
}

// ---------------- scan ----------------
__global__ void k_scan(float* __restrict__ out, int T, int write_aux) {
    if (threadIdx.x == 0 && blockIdx.x == 0) {
        int o = 0;
        float aux = 0.f;
        for (int e = 0; e < NE; e++) {
            g_off[e] = o; g_cursor[e] = o;
            float f = (float)g_counts[e] / (float)(T * 2);
            float P = g_psum[e] / (float)T;
            aux += f * P;
            o += g_counts[e];
        }
        g_off[NE] = o;
        if (write_aux) out[(size_t)T * DIM] = (float)NE * aux;
    }
}

// ---------------- scatter ----------------
__global__ void k_scatter(int T) {
    int t = blockIdx.x * blockDim.x + threadIdx.x;
    if (t < T) {
#pragma unroll
        for (int k = 0; k < 2; k++) {
            int e = g_te[2 * t + k];
            int pos = atomicAdd(&g_cursor[e], 1);
            g_assign[pos] = t;
            g_slot[2 * t + k] = pos;
        }
    }
}

// ---------------- pipelined bf16x3 HMMA GEMM: CTA 128x256, warp 64x64 ----------------
// BK=64 (row = 128B line), SW128 swizzle, 2-stage cp.async ring (96KB/stage).
#define BK 64
#define STG 2
#define TILE_A_B 16384                  // 128 rows x 128B
#define TILE_B_B 32768                  // 256 rows x 128B
#define B_HI (2 * TILE_A_B)
#define B_LO (B_HI + TILE_B_B)
#define STAGE_B (2 * TILE_A_B + 2 * TILE_B_B)   // 98304
#define GEMM_SMEM (STG * STAGE_B)               // 196608

template <int EPI>
__global__ __launch_bounds__(256) void k_gemm_p(
    const bf16* __restrict__ Ahi, const bf16* __restrict__ Alo,
    const bf16* __restrict__ BhiT, const bf16* __restrict__ BloT,
    float* __restrict__ C, const float* __restrict__ Gbuf,
    bf16* __restrict__ Hhi, bf16* __restrict__ Hlo,
    const int* __restrict__ seg_off,
    int M, int N, int K, long strideB, int NST)
{
    int m_lo = 0, m_hi = M;
    const bf16* Bh = BhiT;
    const bf16* Bl = BloT;
    if (seg_off) {
        int s = blockIdx.z;
        m_lo = seg_off[s]; m_hi = seg_off[s + 1];
        Bh += (size_t)s * strideB;
        Bl += (size_t)s * strideB;
    }
    int m0 = m_lo + blockIdx.y * 128;
    if (m0 >= m_hi) return;
    int n0 = blockIdx.x * 256;

    extern __shared__ __align__(1024) char sm[];
    int tid = threadIdx.x, lane = tid & 31, wid = tid >> 5;
    int wm = wid >> 2, wn = wid & 3;

    unsigned sbase;
    asm("{ .reg .u64 t; cvta.to.shared.u64 t, %1; cvt.u32.u64 %0, t; }"
        : "=r"(sbase) : "l"(sm));

    // ---- load addressing ----
    int chunk = tid & 7;
    int r0 = tid >> 3;                  // 0..31
    unsigned rowA[4];
#pragma unroll
    for (int j = 0; j < 4; j++) {
        int r = r0 + 32 * j;
        int gr = m0 + r; if (gr > M - 1) gr = M - 1;
        rowA[j] = (unsigned)((size_t)gr * K * 2) + (unsigned)(chunk * 16);
    }
    unsigned rowB0 = (unsigned)((size_t)(n0 + r0) * K * 2) + (unsigned)(chunk * 16);
    unsigned rowBstep = (unsigned)(32 * K * 2);
    unsigned dst0 = (unsigned)(r0 * 128 + ((chunk * 16) ^ ((r0 & 7) << 4)));

    auto load_stage = [&](int stage, int buf) {
        unsigned d = sbase + (unsigned)buf * STAGE_B + dst0;
        unsigned ko = (unsigned)(stage * BK * 2);
#pragma unroll
        for (int j = 0; j < 4; j++) {
            unsigned dj = d + (unsigned)j * 4096;
            CPA16(dj,            (const char*)Ahi + rowA[j] + ko);
            CPA16(dj + TILE_A_B, (const char*)Alo + rowA[j] + ko);
        }
#pragma unroll
        for (int j = 0; j < 8; j++) {
            unsigned dj = d + (unsigned)j * 4096;
            unsigned rb = rowB0 + (unsigned)j * rowBstep + ko;
            CPA16(dj + B_HI, (const char*)Bh + rb);
            CPA16(dj + B_LO, (const char*)Bl + rb);
        }
    };

    // ---- accumulators ----
    float acc[4][8][4];
#pragma unroll
    for (int i = 0; i < 4; i++)
#pragma unroll
        for (int j = 0; j < 8; j++)
#pragma unroll
            for (int r = 0; r < 4; r++) acc[i][j][r] = 0.f;

    unsigned laneRow = (unsigned)((lane & 15) * 128);
    unsigned chunkb = (unsigned)((lane >> 4) << 4);
    unsigned swx = (unsigned)((lane & 7) << 4);

    // ---- prologue ----
    if (0 < NST) load_stage(0, 0);
    CP_COMMIT();
    if (1 < NST) load_stage(1, 1);
    CP_COMMIT();

    for (int i = 0; i < NST; i++) {
        CP_WAIT1();
        __syncthreads();

        unsigned tb = sbase + (unsigned)(i & 1) * STAGE_B;

#pragma unroll
        for (int ks = 0; ks < 4; ks++) {
            unsigned xoff = (((unsigned)(ks * 32)) | chunkb) ^ swx;
            unsigned bh[8][2], bl[8][2];
#pragma unroll
            for (int nb = 0; nb < 4; nb++) {
                unsigned ro = (unsigned)((wn * 64 + nb * 16) * 128) + laneRow + xoff;
                unsigned t[4];
                ldsm4(t, tb + B_HI + ro);
                bh[2 * nb][0] = t[0]; bh[2 * nb][1] = t[2];
                bh[2 * nb + 1][0] = t[1]; bh[2 * nb + 1][1] = t[3];
                ldsm4(t, tb + B_LO + ro);
                bl[2 * nb][0] = t[0]; bl[2 * nb][1] = t[2];
                bl[2 * nb + 1][0] = t[1]; bl[2 * nb + 1][1] = t[3];
            }
            unsigned ah[4][4], al[4][4];
#pragma unroll
            for (int mi = 0; mi < 4; mi++) {
                unsigned ro = (unsigned)((wm * 64 + mi * 16) * 128) + laneRow + xoff;
                ldsm4(ah[mi], tb + ro);
                ldsm4(al[mi], tb + TILE_A_B + ro);
            }
#pragma unroll
            for (int mi = 0; mi < 4; mi++)
#pragma unroll
                for (int ni = 0; ni < 8; ni++) mma_bf16(acc[mi][ni], ah[mi], bh[ni]);
#pragma unroll
            for (int mi = 0; mi < 4; mi++)
#pragma unroll
                for (int ni = 0; ni < 8; ni++) mma_bf16(acc[mi][ni], al[mi], bh[ni]);
#pragma unroll
            for (int mi = 0; mi < 4; mi++)
#pragma unroll
                for (int ni = 0; ni < 8; ni++) mma_bf16(acc[mi][ni], ah[mi], bl[ni]);
        }
        __syncthreads();
        if (i + 2 < NST) load_stage(i + 2, i & 1);
        CP_COMMIT();
    }

    // ---- epilogue ----
    int mrow = m0 + wm * 64 + (lane >> 2);
    int mcol = n0 + wn * 64 + ((lane & 3) << 1);
#pragma unroll
    for (int mi = 0; mi < 4; mi++) {
#pragma unroll
        for (int half = 0; half < 2; half++) {
            int r = mrow + mi * 16 + half * 8;
            if (r >= m_hi) continue;
#pragma unroll
            for (int ni = 0; ni < 8; ni++) {
                int c = mcol + ni * 8;
                size_t idx = (size_t)r * N + c;
                float v0 = acc[mi][ni][2 * half];
                float v1 = acc[mi][ni][2 * half + 1];
                if (EPI == 0) {
                    *(float2*)(C + idx) = make_float2(v0, v1);
                } else {
                    float2 g = *(const float2*)(Gbuf + idx);
                    float h0 = silu_f(g.x) * v0;
                    float h1 = silu_f(g.y) * v1;
                    bf16 hh0 = __float2bfloat16(h0);
                    bf16 hh1 = __float2bfloat16(h1);
                    bf16 hl0 = __float2bfloat16(h0 - __bfloat162float(hh0));
                    bf16 hl1 = __float2bfloat16(h1 - __bfloat162float(hh1));
                    *(__nv_bfloat162*)(Hhi + idx) = __nv_bfloat162(hh0, hh1);
                    *(__nv_bfloat162*)(Hlo + idx) = __nv_bfloat162(hl0, hl1);
                }
            }
        }
    }
}

// ---------------- combine ----------------
__global__ void k_combine(float* __restrict__ out, const float* __restrict__ pair, int T) {
    int t = blockIdx.x;
    float w0 = g_tw[2 * t], w1 = g_tw[2 * t + 1];
    size_t p0 = (size_t)g_slot[2 * t] * DIM;
    size_t p1 = (size_t)g_slot[2 * t + 1] * DIM;
    size_t ob = (size_t)t * DIM;
    for (int d = threadIdx.x * 4; d < DIM; d += blockDim.x * 4) {
        float4 a = *(const float4*)(pair + p0 + d);
        float4 b = *(const float4*)(pair + p1 + d);
        float4 o = *(const float4*)(out + ob + d);
        o.x += w0 * a.x + w1 * b.x;
        o.y += w0 * a.y + w1 * b.y;
        o.z += w0 * a.z + w1 * b.z;
        o.w += w0 * a.w + w1 * b.w;
        *(float4*)(out + ob + d) = o;
    }
}

// ---------------- launch ----------------
extern "C" void kernel_launch(void* const* d_in, const int* in_sizes, int n_in,
                              void* d_out, int out_size) {
    const float* x  = (const float*)d_in[0];
    const float* gw = (const float*)d_in[1];
    const float* sg = (const float*)d_in[2];
    const float* su = (const float*)d_in[3];
    const float* sd = (const float*)d_in[4];
    const float* eg = (const float*)d_in[5];
    const float* eu = (const float*)d_in[6];
    const float* ed = (const float*)d_in[7];
    float* out = (float*)d_out;

    int T = in_sizes[0] / DIM;       // 8192
    int A2 = 2 * T;

    float *pG, *pPair;
    int *pOff;
    bf16 *pXhi, *pXlo, *pXGhi, *pXGlo, *pHhi, *pHlo;
    bf16 *pSGhi, *pSGlo, *pSUhi, *pSUlo, *pSDhi, *pSDlo;
    bf16 *pEGhi, *pEGlo, *pEUhi, *pEUlo, *pEDhi, *pEDlo;
    cudaGetSymbolAddress((void**)&pG, g_G);
    cudaGetSymbolAddress((void**)&pPair, g_pair);
    cudaGetSymbolAddress((void**)&pOff, g_off);
    cudaGetSymbolAddress((void**)&pXhi, g_xhi);
    cudaGetSymbolAddress((void**)&pXlo, g_xlo);
    cudaGetSymbolAddress((void**)&pXGhi, g_xghi);
    cudaGetSymbolAddress((void**)&pXGlo, g_xglo);
    cudaGetSymbolAddress((void**)&pHhi, g_Hhi);
    cudaGetSymbolAddress((void**)&pHlo, g_Hlo);
    cudaGetSymbolAddress((void**)&pSGhi, g_sgThi);
    cudaGetSymbolAddress((void**)&pSGlo, g_sgTlo);
    cudaGetSymbolAddress((void**)&pSUhi, g_suThi);
    cudaGetSymbolAddress((void**)&pSUlo, g_suTlo);
    cudaGetSymbolAddress((void**)&pSDhi, g_sdThi);
    cudaGetSymbolAddress((void**)&pSDlo, g_sdTlo);
    cudaGetSymbolAddress((void**)&pEGhi, g_egThi);
    cudaGetSymbolAddress((void**)&pEGlo, g_egTlo);
    cudaGetSymbolAddress((void**)&pEUhi, g_euThi);
    cudaGetSymbolAddress((void**)&pEUlo, g_euTlo);
    cudaGetSymbolAddress((void**)&pEDhi, g_edThi);
    cudaGetSymbolAddress((void**)&pEDlo, g_edTlo);

    cudaFuncSetAttribute(k_gemm_p<0>, cudaFuncAttributeMaxDynamicSharedMemorySize, GEMM_SMEM);
    cudaFuncSetAttribute(k_gemm_p<1>, cudaFuncAttributeMaxDynamicSharedMemorySize, GEMM_SMEM);

    k_init<<<1, 32>>>();
    k_router<<<(T + 7) / 8, 256>>>(x, gw, T);
    k_scan<<<1, 1>>>(out, T, (size_t)out_size > (size_t)T * DIM ? 1 : 0);
    k_scatter<<<(T + 255) / 256, 256>>>(T);

    // splits / transposes / gather
    k_split<<<(T * DIM / 4 + 255) / 256, 256>>>((const float4*)x, (__nv_bfloat162*)pXhi,
                                                (__nv_bfloat162*)pXlo, T * DIM / 4);
    k_gsplit<<<A2, 256>>>(x, (__nv_bfloat162*)pXGhi, (__nv_bfloat162*)pXGlo);
    k_tsplit<<<dim3(IDIM / 32, DIM / 32, 1), 256>>>(sg, pSGhi, pSGlo, DIM, IDIM);
    k_tsplit<<<dim3(IDIM / 32, DIM / 32, 1), 256>>>(su, pSUhi, pSUlo, DIM, IDIM);
    k_tsplit<<<dim3(DIM / 32, IDIM / 32, 1), 256>>>(sd, pSDhi, pSDlo, IDIM, DIM);
    k_tsplit<<<dim3(IDIM / 32, DIM / 32, NE), 256>>>(eg, pEGhi, pEGlo, DIM, IDIM);
    k_tsplit<<<dim3(IDIM / 32, DIM / 32, NE), 256>>>(eu, pEUhi, pEUlo, DIM, IDIM);
    k_tsplit<<<dim3(DIM / 32, IDIM / 32, NE), 256>>>(ed, pEDhi, pEDlo, IDIM, DIM);

    // shared expert
    k_gemm_p<0><<<dim3(IDIM / 256, T / 128, 1), 256, GEMM_SMEM>>>(
        pXhi, pXlo, pSGhi, pSGlo, pG, nullptr, nullptr, nullptr,
        nullptr, T, IDIM, DIM, 0, DIM / BK);
    k_gemm_p<1><<<dim3(IDIM / 256, T / 128, 1), 256, GEMM_SMEM>>>(
        pXhi, pXlo, pSUhi, pSUlo, nullptr, pG, pHhi, pHlo,
        nullptr, T, IDIM, DIM, 0, DIM / BK);
    k_gemm_p<0><<<dim3(DIM / 256, T / 128, 1), 256, GEMM_SMEM>>>(
        pHhi, pHlo, pSDhi, pSDlo, out, nullptr, nullptr, nullptr,
        nullptr, T, DIM, IDIM, 0, IDIM / BK);

    // routed experts
    int mt = (A2 + 127) / 128;
    k_gemm_p<0><<<dim3(IDIM / 256, mt, NE), 256, GEMM_SMEM>>>(
        pXGhi, pXGlo, pEGhi, pEGlo, pG, nullptr, nullptr, nullptr,
        pOff, A2, IDIM, DIM, (long)DIM * IDIM, DIM / BK);
    k_gemm_p<1><<<dim3(IDIM / 256, mt, NE), 256, GEMM_SMEM>>>(
        pXGhi, pXGlo, pEUhi, pEUlo, nullptr, pG, pHhi, pHlo,
        pOff, A2, IDIM, DIM, (long)DIM * IDIM, DIM / BK);
    k_gemm_p<0><<<dim3(DIM / 256, mt, NE), 256, GEMM_SMEM>>>(
        pHhi, pHlo, pEDhi, pEDlo, pPair, nullptr, nullptr, nullptr,
        pOff, A2, DIM, IDIM, (long)IDIM * DIM, IDIM / BK);

    k_combine<<<T, 256>>>(out, pPair, T);
}